// round 9
// baseline (speedup 1.0000x reference)
#include <cuda_runtime.h>
#include <cuda_bf16.h>
#include <math.h>
#include <stdint.h>

// Problem constants
#define BB 4
#define SS 2048
#define DD 1024
#define HH 16
#define HD 64
#define MROWS (BB * SS)   // 8192

// ---------------------------------------------------------------------------
// Scratch (device globals: allocation-free)
// ---------------------------------------------------------------------------
__device__ __align__(16) __nv_bfloat16 g_xh[MROWS * DD];
__device__ __align__(16) __nv_bfloat16 g_xl[MROWS * DD];
__device__ __align__(16) __nv_bfloat16 g_wh[4 * DD * DD];
__device__ __align__(16) __nv_bfloat16 g_wl[4 * DD * DD];
__device__ __align__(16) __nv_bfloat16 g_ch[MROWS * DD];
__device__ __align__(16) __nv_bfloat16 g_cl[MROWS * DD];
__device__ __align__(16) __nv_bfloat16 g_qh[BB * HH * SS * HD];
__device__ __align__(16) __nv_bfloat16 g_ql[BB * HH * SS * HD];
__device__ __align__(16) __nv_bfloat16 g_kh[BB * HH * SS * HD];
__device__ __align__(16) __nv_bfloat16 g_kl[BB * HH * SS * HD];
__device__ __align__(16) __nv_bfloat16 g_vh[BB * HH * SS * HD];
__device__ __align__(16) __nv_bfloat16 g_vl[BB * HH * SS * HD];

// ---------------------------------------------------------------------------
// Helpers
// ---------------------------------------------------------------------------
__device__ __forceinline__ uint32_t smem_u32(const void* p) {
    uint32_t a;
    asm("{ .reg .u64 t; cvta.to.shared.u64 t, %1; cvt.u32.u64 %0, t; }"
        : "=r"(a) : "l"(p));
    return a;
}

__device__ __forceinline__ void ldsm4(uint32_t* r, uint32_t addr) {
    asm volatile("ldmatrix.sync.aligned.m8n8.x4.shared.b16 {%0,%1,%2,%3}, [%4];"
                 : "=r"(r[0]), "=r"(r[1]), "=r"(r[2]), "=r"(r[3]) : "r"(addr));
}
__device__ __forceinline__ void ldsm4t(uint32_t* r, uint32_t addr) {
    asm volatile("ldmatrix.sync.aligned.m8n8.x4.trans.shared.b16 {%0,%1,%2,%3}, [%4];"
                 : "=r"(r[0]), "=r"(r[1]), "=r"(r[2]), "=r"(r[3]) : "r"(addr));
}

__device__ __forceinline__ void mma16816(float* c, const uint32_t* a, const uint32_t* b) {
    asm volatile("mma.sync.aligned.m16n8k16.row.col.f32.bf16.bf16.f32 "
                 "{%0,%1,%2,%3}, {%4,%5,%6,%7}, {%8,%9}, {%0,%1,%2,%3};"
                 : "+f"(c[0]), "+f"(c[1]), "+f"(c[2]), "+f"(c[3])
                 : "r"(a[0]), "r"(a[1]), "r"(a[2]), "r"(a[3]), "r"(b[0]), "r"(b[1]));
}

#define CP_ASYNC16(dst, src) \
    asm volatile("cp.async.cg.shared.global [%0], [%1], 16;" :: "r"(dst), "l"(src))
#define CP_COMMIT() asm volatile("cp.async.commit_group;" ::: "memory")
#define CP_WAIT0() asm volatile("cp.async.wait_group 0;" ::: "memory")
#define CP_WAIT1() asm volatile("cp.async.wait_group 1;" ::: "memory")

__device__ __forceinline__ uint32_t pk2(__nv_bfloat16 a, __nv_bfloat16 b) {
    return (uint32_t)__bfloat16_as_ushort(a) | ((uint32_t)__bfloat16_as_ushort(b) << 16);
}
__device__ __forceinline__ void split1(float v, __nv_bfloat16& h, __nv_bfloat16& l) {
    h = __float2bfloat16(v);
    l = __float2bfloat16(v - __bfloat162float(h));
}

// ---------------------------------------------------------------------------
// fp32 -> (bf16 hi, bf16 lo) split, vectorized x4
// ---------------------------------------------------------------------------
__global__ __launch_bounds__(256) void split_kernel(
    const float4* __restrict__ src, uint2* __restrict__ hi, uint2* __restrict__ lo, int n4)
{
    int i = blockIdx.x * blockDim.x + threadIdx.x;
    if (i >= n4) return;
    float4 v = src[i];
    __nv_bfloat16 h0, h1, h2, h3, l0, l1, l2, l3;
    split1(v.x, h0, l0); split1(v.y, h1, l1);
    split1(v.z, h2, l2); split1(v.w, h3, l3);
    hi[i] = make_uint2(pk2(h0, h1), pk2(h2, h3));
    lo[i] = make_uint2(pk2(l0, l1), pk2(l2, l3));
}

// ---------------------------------------------------------------------------
// Fused QKV projection GEMM: grid (8, 64, 3), z selects {Q, K, V}.
// HMMA bf16-split, cp.async double-buffered. Epilogue stages fp32 tile in
// smem, applies RoPE (Q,K only) + bf16 hi/lo split, writes [B,H,S,hd].
// ---------------------------------------------------------------------------
#define GK 32
#define NCHUNK (DD / GK)       // 32
#define ROWB 80
#define TILE_SB (128 * ROWB)   // 10240
#define BUF_SB (4 * TILE_SB)   // 40960
#define GEMM_SMEM (2 * BUF_SB) // 81920
#define EROW 132               // fp32 staging row stride (floats)

__global__ __launch_bounds__(256) void gemm_qkv(
    const __nv_bfloat16* __restrict__ Ah, const __nv_bfloat16* __restrict__ Al,
    const __nv_bfloat16* __restrict__ Wh, const __nv_bfloat16* __restrict__ Wl,
    const float* __restrict__ bq, const float* __restrict__ bk,
    const float* __restrict__ bv,
    const float* __restrict__ cosb, const float* __restrict__ sinb,
    __nv_bfloat16* __restrict__ Qh, __nv_bfloat16* __restrict__ Ql,
    __nv_bfloat16* __restrict__ Kh, __nv_bfloat16* __restrict__ Kl,
    __nv_bfloat16* __restrict__ Vh, __nv_bfloat16* __restrict__ Vl)
{
    extern __shared__ char sm[];
    const int tid  = threadIdx.x;
    const int wid  = tid >> 5;
    const int lane = tid & 31;
    const int bm = blockIdx.y * 128;
    const int bn = blockIdx.x * 128;
    const int zi = blockIdx.z;
    const int warp_m = (wid & 1) * 64;
    const int warp_n = (wid >> 1) * 32;

    const float* bias = (zi == 0) ? bq : (zi == 1) ? bk : bv;
    const __nv_bfloat16* Bh = Wh + (size_t)zi * DD * DD;
    const __nv_bfloat16* Bl = Wl + (size_t)zi * DD * DD;

    const uint32_t sb = smem_u32(sm);

    const char* gsrc[4] = {
        (const char*)(Ah + (size_t)bm * DD), (const char*)(Al + (size_t)bm * DD),
        (const char*)(Bh + (size_t)bn * DD), (const char*)(Bl + (size_t)bn * DD) };

    float acc[4][4][4];
#pragma unroll
    for (int i = 0; i < 4; i++)
#pragma unroll
        for (int j = 0; j < 4; j++)
#pragma unroll
            for (int q = 0; q < 4; q++) acc[i][j][q] = 0.0f;

    auto issue_chunk = [&](int c, int buf) {
        const int koff = c * 64;
        const uint32_t sdst = sb + buf * BUF_SB;
#pragma unroll
        for (int t = 0; t < 4; t++) {
            const char* g = gsrc[t] + koff;
#pragma unroll
            for (int i = 0; i < 2; i++) {
                int idx = i * 256 + tid;
                int row = idx >> 2, seg = idx & 3;
                CP_ASYNC16(sdst + t * TILE_SB + row * ROWB + seg * 16,
                           g + (size_t)row * 2048 + seg * 16);
            }
        }
    };

    issue_chunk(0, 0);
    CP_COMMIT();

    const int lig = lane & 7;
    const int grp = lane >> 3;

    for (int c = 0; c < NCHUNK; c++) {
        const int cur = c & 1;
        if (c + 1 < NCHUNK) { issue_chunk(c + 1, cur ^ 1); CP_COMMIT(); CP_WAIT1(); }
        else                { CP_WAIT0(); }
        __syncthreads();

        const uint32_t bufb = sb + cur * BUF_SB;
#pragma unroll
        for (int ks = 0; ks < 2; ks++) {
            uint32_t aH[4][4], aL[4][4], bH[2][4], bL[2][4];
            {
                const int arow = warp_m + (grp & 1) * 8 + lig;
                const int aseg = 2 * ks + (grp >> 1);
                const uint32_t aoff = arow * ROWB + aseg * 16;
#pragma unroll
                for (int mi = 0; mi < 4; mi++) {
                    ldsm4(aH[mi], bufb + 0 * TILE_SB + aoff + mi * (16 * ROWB));
                    ldsm4(aL[mi], bufb + 1 * TILE_SB + aoff + mi * (16 * ROWB));
                }
            }
            {
                const int brow = warp_n + (grp >> 1) * 8 + lig;
                const int bseg = 2 * ks + (grp & 1);
                const uint32_t boff = brow * ROWB + bseg * 16;
#pragma unroll
                for (int ni = 0; ni < 2; ni++) {
                    ldsm4(bH[ni], bufb + 2 * TILE_SB + boff + ni * (16 * ROWB));
                    ldsm4(bL[ni], bufb + 3 * TILE_SB + boff + ni * (16 * ROWB));
                }
            }
#pragma unroll
            for (int mi = 0; mi < 4; mi++)
#pragma unroll
                for (int nj = 0; nj < 4; nj++) {
                    const int ni = nj >> 1, pr = (nj & 1) * 2;
                    mma16816(acc[mi][nj], aH[mi], &bH[ni][pr]);
                    mma16816(acc[mi][nj], aH[mi], &bL[ni][pr]);
                    mma16816(acc[mi][nj], aL[mi], &bH[ni][pr]);
                }
        }
        __syncthreads();
    }

    // ---- epilogue: stage fp32 tile in smem, rope+split, scatter ----
    float* st = (float*)sm;
    const int mrow = lane >> 2;
    const int ncol = 2 * (lane & 3);
#pragma unroll
    for (int mi = 0; mi < 4; mi++)
#pragma unroll
        for (int nj = 0; nj < 4; nj++) {
            const int r0 = warp_m + mi * 16 + mrow;
            const int cc = warp_n + nj * 8 + ncol;
            const float b0 = bias[bn + cc], b1 = bias[bn + cc + 1];
#pragma unroll
            for (int half = 0; half < 2; half++) {
                st[(r0 + half * 8) * EROW + cc]     = acc[mi][nj][2 * half + 0] + b0;
                st[(r0 + half * 8) * EROW + cc + 1] = acc[mi][nj][2 * half + 1] + b1;
            }
        }
    __syncthreads();

    // 256 threads: 2 threads per row, each owns one head (64 cols)
    {
        const int row = tid >> 1;            // 0..127
        const int hsel = tid & 1;            // head within tile
        const int m = bm + row;
        const int b = m >> 11, s = m & 2047;
        const int h = (bn >> 6) + hsel;
        const float* src = st + row * EROW + hsel * 64;
        __nv_bfloat16* dh;
        __nv_bfloat16* dl;
        const size_t oidx = ((size_t)(b * HH + h) * SS + s) * HD;
        if (zi == 0)      { dh = Qh + oidx; dl = Ql + oidx; }
        else if (zi == 1) { dh = Kh + oidx; dl = Kl + oidx; }
        else              { dh = Vh + oidx; dl = Vl + oidx; }

        if (zi < 2) {
#pragma unroll
            for (int p4 = 0; p4 < 8; p4++) {
                const int p = p4 * 4;
                float4 x1 = *(const float4*)(src + p);
                float4 x2 = *(const float4*)(src + p + 32);
                float4 c1 = *(const float4*)(cosb + s * HD + p);
                float4 s1 = *(const float4*)(sinb + s * HD + p);
                float4 c2 = *(const float4*)(cosb + s * HD + p + 32);
                float4 s2 = *(const float4*)(sinb + s * HD + p + 32);
                float v1[4] = { x1.x * c1.x - x2.x * s1.x, x1.y * c1.y - x2.y * s1.y,
                                x1.z * c1.z - x2.z * s1.z, x1.w * c1.w - x2.w * s1.w };
                float v2[4] = { x2.x * c2.x + x1.x * s2.x, x2.y * c2.y + x1.y * s2.y,
                                x2.z * c2.z + x1.z * s2.z, x2.w * c2.w + x1.w * s2.w };
                __nv_bfloat16 hh[4], ll[4];
#pragma unroll
                for (int q = 0; q < 4; q++) split1(v1[q], hh[q], ll[q]);
                *(uint2*)(dh + p) = make_uint2(pk2(hh[0], hh[1]), pk2(hh[2], hh[3]));
                *(uint2*)(dl + p) = make_uint2(pk2(ll[0], ll[1]), pk2(ll[2], ll[3]));
#pragma unroll
                for (int q = 0; q < 4; q++) split1(v2[q], hh[q], ll[q]);
                *(uint2*)(dh + p + 32) = make_uint2(pk2(hh[0], hh[1]), pk2(hh[2], hh[3]));
                *(uint2*)(dl + p + 32) = make_uint2(pk2(ll[0], ll[1]), pk2(ll[2], ll[3]));
            }
        } else {
#pragma unroll
            for (int p4 = 0; p4 < 16; p4++) {
                const int p = p4 * 4;
                float4 x = *(const float4*)(src + p);
                __nv_bfloat16 hh[4], ll[4];
                split1(x.x, hh[0], ll[0]); split1(x.y, hh[1], ll[1]);
                split1(x.z, hh[2], ll[2]); split1(x.w, hh[3], ll[3]);
                *(uint2*)(dh + p) = make_uint2(pk2(hh[0], hh[1]), pk2(hh[2], hh[3]));
                *(uint2*)(dl + p) = make_uint2(pk2(ll[0], ll[1]), pk2(ll[2], ll[3]));
            }
        }
    }
}

// ---------------------------------------------------------------------------
// Output GEMM: ctx(hi/lo) @ Wo^T + bo -> fp32 row-major
// ---------------------------------------------------------------------------
__global__ __launch_bounds__(256) void gemm_out(
    const __nv_bfloat16* __restrict__ Ah, const __nv_bfloat16* __restrict__ Al,
    const __nv_bfloat16* __restrict__ Bh, const __nv_bfloat16* __restrict__ Bl,
    const float* __restrict__ bias, float* __restrict__ C)
{
    extern __shared__ char sm[];
    const int tid  = threadIdx.x;
    const int wid  = tid >> 5;
    const int lane = tid & 31;
    const int bm = blockIdx.y * 128;
    const int bn = blockIdx.x * 128;
    const int warp_m = (wid & 1) * 64;
    const int warp_n = (wid >> 1) * 32;

    const uint32_t sb = smem_u32(sm);
    const char* gsrc[4] = {
        (const char*)(Ah + (size_t)bm * DD), (const char*)(Al + (size_t)bm * DD),
        (const char*)(Bh + (size_t)bn * DD), (const char*)(Bl + (size_t)bn * DD) };

    float acc[4][4][4];
#pragma unroll
    for (int i = 0; i < 4; i++)
#pragma unroll
        for (int j = 0; j < 4; j++)
#pragma unroll
            for (int q = 0; q < 4; q++) acc[i][j][q] = 0.0f;

    auto issue_chunk = [&](int c, int buf) {
        const int koff = c * 64;
        const uint32_t sdst = sb + buf * BUF_SB;
#pragma unroll
        for (int t = 0; t < 4; t++) {
            const char* g = gsrc[t] + koff;
#pragma unroll
            for (int i = 0; i < 2; i++) {
                int idx = i * 256 + tid;
                int row = idx >> 2, seg = idx & 3;
                CP_ASYNC16(sdst + t * TILE_SB + row * ROWB + seg * 16,
                           g + (size_t)row * 2048 + seg * 16);
            }
        }
    };

    issue_chunk(0, 0);
    CP_COMMIT();

    const int lig = lane & 7;
    const int grp = lane >> 3;

    for (int c = 0; c < NCHUNK; c++) {
        const int cur = c & 1;
        if (c + 1 < NCHUNK) { issue_chunk(c + 1, cur ^ 1); CP_COMMIT(); CP_WAIT1(); }
        else                { CP_WAIT0(); }
        __syncthreads();

        const uint32_t bufb = sb + cur * BUF_SB;
#pragma unroll
        for (int ks = 0; ks < 2; ks++) {
            uint32_t aH[4][4], aL[4][4], bH[2][4], bL[2][4];
            {
                const int arow = warp_m + (grp & 1) * 8 + lig;
                const int aseg = 2 * ks + (grp >> 1);
                const uint32_t aoff = arow * ROWB + aseg * 16;
#pragma unroll
                for (int mi = 0; mi < 4; mi++) {
                    ldsm4(aH[mi], bufb + 0 * TILE_SB + aoff + mi * (16 * ROWB));
                    ldsm4(aL[mi], bufb + 1 * TILE_SB + aoff + mi * (16 * ROWB));
                }
            }
            {
                const int brow = warp_n + (grp >> 1) * 8 + lig;
                const int bseg = 2 * ks + (grp & 1);
                const uint32_t boff = brow * ROWB + bseg * 16;
#pragma unroll
                for (int ni = 0; ni < 2; ni++) {
                    ldsm4(bH[ni], bufb + 2 * TILE_SB + boff + ni * (16 * ROWB));
                    ldsm4(bL[ni], bufb + 3 * TILE_SB + boff + ni * (16 * ROWB));
                }
            }
#pragma unroll
            for (int mi = 0; mi < 4; mi++)
#pragma unroll
                for (int nj = 0; nj < 4; nj++) {
                    const int ni = nj >> 1, pr = (nj & 1) * 2;
                    mma16816(acc[mi][nj], aH[mi], &bH[ni][pr]);
                    mma16816(acc[mi][nj], aH[mi], &bL[ni][pr]);
                    mma16816(acc[mi][nj], aL[mi], &bH[ni][pr]);
                }
        }
        __syncthreads();
    }

    const int mrow = lane >> 2;
    const int ncol = 2 * (lane & 3);
#pragma unroll
    for (int mi = 0; mi < 4; mi++)
#pragma unroll
        for (int nj = 0; nj < 4; nj++) {
            const int m0 = bm + warp_m + mi * 16 + mrow;
            const int n  = bn + warp_n + nj * 8 + ncol;
            const float b0 = bias[n], b1 = bias[n + 1];
#pragma unroll
            for (int half = 0; half < 2; half++) {
                const int m = m0 + half * 8;
                *(float2*)(C + (size_t)m * DD + n) =
                    make_float2(acc[mi][nj][2 * half + 0] + b0,
                                acc[mi][nj][2 * half + 1] + b1);
            }
        }
}

// ---------------------------------------------------------------------------
// HMMA flash attention (causal). Block = 128 q-rows, 4 warps, warp = 32 rows
// (two m16 tiles) -> K/V fragments shared across both, halving LDS traffic.
// ---------------------------------------------------------------------------
#define FROW 144
#define KTILE (64 * FROW)        // 9216
#define FBUF (4 * KTILE)         // 36864: Kh,Kl,Vh,Vl
#define QTILE (128 * FROW)       // 18432
#define FQOFF (2 * FBUF)         // 73728
#define FSMEM (FQOFF + 2 * QTILE)  // 110592

__global__ __launch_bounds__(128) void flash_mma(
    const __nv_bfloat16* __restrict__ Qh, const __nv_bfloat16* __restrict__ Ql,
    const __nv_bfloat16* __restrict__ Kh, const __nv_bfloat16* __restrict__ Kl,
    const __nv_bfloat16* __restrict__ Vh, const __nv_bfloat16* __restrict__ Vl,
    __nv_bfloat16* __restrict__ ctx_h, __nv_bfloat16* __restrict__ ctx_l)
{
    extern __shared__ char sm[];
    const int tid  = threadIdx.x;
    const int wid  = tid >> 5;      // 0..3
    const int lane = tid & 31;
    const int qb = blockIdx.x;      // 0..15
    const int bh = blockIdx.y;      // 0..63
    const uint32_t sb = smem_u32(sm);
    const size_t bhoff = (size_t)bh * SS * HD;
    const int ntiles = 2 * qb + 2;

    const int lig = lane & 7;
    const int grp = lane >> 3;

    auto issue_kv = [&](int kt, int buf) {
        const __nv_bfloat16* srcs[4] = {
            Kh + bhoff + (size_t)kt * 64 * HD, Kl + bhoff + (size_t)kt * 64 * HD,
            Vh + bhoff + (size_t)kt * 64 * HD, Vl + bhoff + (size_t)kt * 64 * HD };
        const uint32_t dbase = sb + buf * FBUF;
#pragma unroll
        for (int t = 0; t < 4; t++) {
            const char* g = (const char*)srcs[t];
            int idx = tid;          // 512 segs / 128 threads = 4
#pragma unroll
            for (int i = 0; i < 4; i++) {
                int row = idx >> 3, seg = idx & 7;
                CP_ASYNC16(dbase + t * KTILE + row * FROW + seg * 16,
                           g + row * 128 + seg * 16);
                idx += 128;
            }
        }
    };

    issue_kv(0, 0);
    CP_COMMIT();
    {
        const char* qsrc[2] = { (const char*)(Qh + bhoff + (size_t)qb * 128 * HD),
                                (const char*)(Ql + bhoff + (size_t)qb * 128 * HD) };
#pragma unroll
        for (int t = 0; t < 2; t++) {
            int idx = tid;          // 1024 segs / 128 threads = 8
#pragma unroll
            for (int i = 0; i < 8; i++) {
                int row = idx >> 3, seg = idx & 7;
                CP_ASYNC16(sb + FQOFF + t * QTILE + row * FROW + seg * 16,
                           qsrc[t] + row * 128 + seg * 16);
                idx += 128;
            }
        }
        CP_COMMIT();
    }
    CP_WAIT0();
    __syncthreads();

    float o[2][8][4];
#pragma unroll
    for (int mi = 0; mi < 2; mi++)
#pragma unroll
        for (int nt = 0; nt < 8; nt++)
#pragma unroll
            for (int q = 0; q < 4; q++) o[mi][nt][q] = 0.0f;
    float mA[2] = {-1e30f, -1e30f}, mB[2] = {-1e30f, -1e30f};
    float lA[2] = {0.0f, 0.0f},     lB[2] = {0.0f, 0.0f};

    for (int kt = 0; kt < ntiles; kt++) {
        const int cur = kt & 1;
        if (kt + 1 < ntiles) { issue_kv(kt + 1, cur ^ 1); CP_COMMIT(); CP_WAIT1(); }
        else                 { CP_WAIT0(); }
        __syncthreads();

        const uint32_t kb = sb + cur * FBUF;

        // ---- scores: K frags shared across both m-tiles ----
        float sc[2][8][4];
#pragma unroll
        for (int mi = 0; mi < 2; mi++)
#pragma unroll
            for (int nt = 0; nt < 8; nt++)
#pragma unroll
                for (int q = 0; q < 4; q++) sc[mi][nt][q] = 0.0f;

#pragma unroll
        for (int kc = 0; kc < 4; kc++) {
            uint32_t kh_f[4][4], kl_f[4][4];
            const int krow = (grp >> 1) * 8 + lig;
            const int kseg = 2 * kc + (grp & 1);
#pragma unroll
            for (int p = 0; p < 4; p++) {
                const uint32_t a = kb + (krow + p * 16) * FROW + kseg * 16;
                ldsm4(kh_f[p], a);
                ldsm4(kl_f[p], a + KTILE);
            }
#pragma unroll
            for (int mi = 0; mi < 2; mi++) {
                uint32_t qh_f[4], ql_f[4];
                const int qrow = wid * 32 + mi * 16 + (grp & 1) * 8 + lig;
                const uint32_t qa = sb + FQOFF + qrow * FROW + (2 * kc + (grp >> 1)) * 16;
                ldsm4(qh_f, qa);
                ldsm4(ql_f, qa + QTILE);
#pragma unroll
                for (int nt = 0; nt < 8; nt++) {
                    const int p = nt >> 1, pr = (nt & 1) * 2;
                    mma16816(sc[mi][nt], qh_f, &kh_f[p][pr]);
                    mma16816(sc[mi][nt], qh_f, &kl_f[p][pr]);
                    mma16816(sc[mi][nt], ql_f, &kh_f[p][pr]);
                }
            }
        }

        // ---- softmax + P frags (per m-tile) ----
        uint32_t ph_f[2][4][4], pl_f[2][4][4];
#pragma unroll
        for (int mi = 0; mi < 2; mi++) {
#pragma unroll
            for (int nt = 0; nt < 8; nt++)
#pragma unroll
                for (int q = 0; q < 4; q++) sc[mi][nt][q] *= 0.125f;

            if (kt >= 2 * qb) {
                const int grow0 = qb * 128 + wid * 32 + mi * 16 + (lane >> 2);
#pragma unroll
                for (int nt = 0; nt < 8; nt++)
#pragma unroll
                    for (int q = 0; q < 4; q++) {
                        const int col = kt * 64 + nt * 8 + 2 * (lane & 3) + (q & 1);
                        const int row = grow0 + ((q >> 1) << 3);
                        if (col > row) sc[mi][nt][q] = -1e30f;
                    }
            }

            float mx0 = -1e30f, mx1 = -1e30f;
#pragma unroll
            for (int nt = 0; nt < 8; nt++) {
                mx0 = fmaxf(mx0, fmaxf(sc[mi][nt][0], sc[mi][nt][1]));
                mx1 = fmaxf(mx1, fmaxf(sc[mi][nt][2], sc[mi][nt][3]));
            }
            mx0 = fmaxf(mx0, __shfl_xor_sync(0xffffffff, mx0, 1));
            mx0 = fmaxf(mx0, __shfl_xor_sync(0xffffffff, mx0, 2));
            mx1 = fmaxf(mx1, __shfl_xor_sync(0xffffffff, mx1, 1));
            mx1 = fmaxf(mx1, __shfl_xor_sync(0xffffffff, mx1, 2));

            const float mn0 = fmaxf(mA[mi], mx0);
            const float mn1 = fmaxf(mB[mi], mx1);
            const float c0 = __expf(mA[mi] - mn0);
            const float c1 = __expf(mB[mi] - mn1);
            mA[mi] = mn0; mB[mi] = mn1;
            lA[mi] *= c0; lB[mi] *= c1;
#pragma unroll
            for (int nt = 0; nt < 8; nt++) {
                o[mi][nt][0] *= c0; o[mi][nt][1] *= c0;
                o[mi][nt][2] *= c1; o[mi][nt][3] *= c1;
            }

#pragma unroll
            for (int nt = 0; nt < 8; nt++) {
                const float p0 = __expf(sc[mi][nt][0] - mn0);
                const float p1 = __expf(sc[mi][nt][1] - mn0);
                const float p2 = __expf(sc[mi][nt][2] - mn1);
                const float p3 = __expf(sc[mi][nt][3] - mn1);
                lA[mi] += p0 + p1;
                lB[mi] += p2 + p3;
                __nv_bfloat16 h0, h1, h2, h3, e0, e1, e2, e3;
                split1(p0, h0, e0); split1(p1, h1, e1);
                split1(p2, h2, e2); split1(p3, h3, e3);
                const int kc = nt >> 1, hf = (nt & 1) * 2;
                ph_f[mi][kc][hf + 0] = pk2(h0, h1);
                ph_f[mi][kc][hf + 1] = pk2(h2, h3);
                pl_f[mi][kc][hf + 0] = pk2(e0, e1);
                pl_f[mi][kc][hf + 1] = pk2(e2, e3);
            }
        }

        // ---- PV: V frags shared across both m-tiles ----
        const uint32_t vb = kb + 2 * KTILE;
#pragma unroll
        for (int kc = 0; kc < 4; kc++) {
            uint32_t vh_f[4][4], vl_f[4][4];
            const int vrow = kc * 16 + (grp & 1) * 8 + lig;
#pragma unroll
            for (int p = 0; p < 4; p++) {
                const uint32_t a = vb + vrow * FROW + (2 * p + (grp >> 1)) * 16;
                ldsm4t(vh_f[p], a);
                ldsm4t(vl_f[p], a + KTILE);
            }
#pragma unroll
            for (int mi = 0; mi < 2; mi++)
#pragma unroll
                for (int nt = 0; nt < 8; nt++) {
                    const int p = nt >> 1, pr = (nt & 1) * 2;
                    mma16816(o[mi][nt], ph_f[mi][kc], &vh_f[p][pr]);
                    mma16816(o[mi][nt], ph_f[mi][kc], &vl_f[p][pr]);
                    mma16816(o[mi][nt], pl_f[mi][kc], &vh_f[p][pr]);
                }
        }
        __syncthreads();
    }

    // ---- finalize ----
    const int b = bh >> 4;
    const int h = bh & 15;
#pragma unroll
    for (int mi = 0; mi < 2; mi++) {
        float l0 = lA[mi], l1 = lB[mi];
        l0 += __shfl_xor_sync(0xffffffff, l0, 1);
        l0 += __shfl_xor_sync(0xffffffff, l0, 2);
        l1 += __shfl_xor_sync(0xffffffff, l1, 1);
        l1 += __shfl_xor_sync(0xffffffff, l1, 2);
        const float i0 = 1.0f / l0;
        const float i1 = 1.0f / l1;
        const int s0 = qb * 128 + wid * 32 + mi * 16 + (lane >> 2);
        const int s1 = s0 + 8;
#pragma unroll
        for (int nt = 0; nt < 8; nt++) {
            const int col = h * 64 + nt * 8 + 2 * (lane & 3);
            const size_t idx0 = ((size_t)(b * SS + s0)) * DD + col;
            const size_t idx1 = ((size_t)(b * SS + s1)) * DD + col;
            __nv_bfloat16 h0, h1, e0, e1;
            split1(o[mi][nt][0] * i0, h0, e0); split1(o[mi][nt][1] * i0, h1, e1);
            *(uint32_t*)(ctx_h + idx0) = pk2(h0, h1);
            *(uint32_t*)(ctx_l + idx0) = pk2(e0, e1);
            split1(o[mi][nt][2] * i1, h0, e0); split1(o[mi][nt][3] * i1, h1, e1);
            *(uint32_t*)(ctx_h + idx1) = pk2(h0, h1);
            *(uint32_t*)(ctx_l + idx1) = pk2(e0, e1);
        }
    }
}

// ---------------------------------------------------------------------------
// Launch
// ---------------------------------------------------------------------------
extern "C" void kernel_launch(void* const* d_in, const int* in_sizes, int n_in,
                              void* d_out, int out_size)
{
    const float* x    = (const float*)d_in[0];
    const float* cosb = (const float*)d_in[2];
    const float* sinb = (const float*)d_in[3];
    const float* Wq = (const float*)d_in[4];
    const float* bq = (const float*)d_in[5];
    const float* Wk = (const float*)d_in[6];
    const float* bk = (const float*)d_in[7];
    const float* Wv = (const float*)d_in[8];
    const float* bv = (const float*)d_in[9];
    const float* Wo = (const float*)d_in[10];
    const float* bo = (const float*)d_in[11];
    float* out = (float*)d_out;

    __nv_bfloat16 *xh, *xl, *wh, *wl, *ch, *cl, *qh, *ql, *kh, *kl, *vh, *vl;
    cudaGetSymbolAddress((void**)&xh, g_xh);
    cudaGetSymbolAddress((void**)&xl, g_xl);
    cudaGetSymbolAddress((void**)&wh, g_wh);
    cudaGetSymbolAddress((void**)&wl, g_wl);
    cudaGetSymbolAddress((void**)&ch, g_ch);
    cudaGetSymbolAddress((void**)&cl, g_cl);
    cudaGetSymbolAddress((void**)&qh, g_qh);
    cudaGetSymbolAddress((void**)&ql, g_ql);
    cudaGetSymbolAddress((void**)&kh, g_kh);
    cudaGetSymbolAddress((void**)&kl, g_kl);
    cudaGetSymbolAddress((void**)&vh, g_vh);
    cudaGetSymbolAddress((void**)&vl, g_vl);

    cudaFuncSetAttribute(gemm_qkv, cudaFuncAttributeMaxDynamicSharedMemorySize, GEMM_SMEM);
    cudaFuncSetAttribute(gemm_out, cudaFuncAttributeMaxDynamicSharedMemorySize, GEMM_SMEM);
    cudaFuncSetAttribute(flash_mma, cudaFuncAttributeMaxDynamicSharedMemorySize, FSMEM);

    {
        int n4 = MROWS * DD / 4;
        split_kernel<<<(n4 + 255) / 256, 256>>>((const float4*)x, (uint2*)xh, (uint2*)xl, n4);
        const float* Ws[4] = {Wq, Wk, Wv, Wo};
        int w4 = DD * DD / 4;
        for (int i = 0; i < 4; i++)
            split_kernel<<<(w4 + 255) / 256, 256>>>((const float4*)Ws[i],
                (uint2*)(wh + (size_t)i * DD * DD), (uint2*)(wl + (size_t)i * DD * DD), w4);
    }

    dim3 gq(DD / 128, MROWS / 128, 3);   // (8, 64, 3)
    gemm_qkv<<<gq, 256, GEMM_SMEM>>>(xh, xl, wh, wl, bq, bk, bv, cosb, sinb,
                                     qh, ql, kh, kl, vh, vl);

    dim3 fg(SS / 128, BB * HH);          // (16, 64)
    flash_mma<<<fg, 128, FSMEM>>>(qh, ql, kh, kl, vh, vl, ch, cl);

    dim3 gg(DD / 128, MROWS / 128);      // (8, 64)
    gemm_out<<<gg, 256, GEMM_SMEM>>>(ch, cl, wh + 3 * (size_t)DD * DD,
                                     wl + 3 * (size_t)DD * DD, bo, out);
}

// round 11
// speedup vs baseline: 1.1068x; 1.1068x over previous
#include <cuda_runtime.h>
#include <cuda_bf16.h>
#include <math.h>
#include <stdint.h>

// Problem constants
#define BB 4
#define SS 2048
#define DD 1024
#define HH 16
#define HD 64
#define MROWS (BB * SS)   // 8192

// ---------------------------------------------------------------------------
// Scratch (device globals: allocation-free)
// ---------------------------------------------------------------------------
__device__ float g_Q[BB * HH * SS * HD];
__device__ float g_K[BB * HH * SS * HD];
__device__ float g_V[BB * HH * SS * HD];
__device__ __align__(16) __nv_bfloat16 g_xh[MROWS * DD];
__device__ __align__(16) __nv_bfloat16 g_xl[MROWS * DD];
__device__ __align__(16) __nv_bfloat16 g_wh[4 * DD * DD];
__device__ __align__(16) __nv_bfloat16 g_wl[4 * DD * DD];
__device__ __align__(16) __nv_bfloat16 g_ch[MROWS * DD];
__device__ __align__(16) __nv_bfloat16 g_cl[MROWS * DD];
__device__ __align__(16) __nv_bfloat16 g_qh[BB * HH * SS * HD];
__device__ __align__(16) __nv_bfloat16 g_ql[BB * HH * SS * HD];
__device__ __align__(16) __nv_bfloat16 g_kh[BB * HH * SS * HD];
__device__ __align__(16) __nv_bfloat16 g_kl[BB * HH * SS * HD];
__device__ __align__(16) __nv_bfloat16 g_vh[BB * HH * SS * HD];
__device__ __align__(16) __nv_bfloat16 g_vl[BB * HH * SS * HD];

// ---------------------------------------------------------------------------
// Helpers
// ---------------------------------------------------------------------------
__device__ __forceinline__ uint32_t smem_u32(const void* p) {
    uint32_t a;
    asm("{ .reg .u64 t; cvta.to.shared.u64 t, %1; cvt.u32.u64 %0, t; }"
        : "=r"(a) : "l"(p));
    return a;
}

__device__ __forceinline__ void ldsm4(uint32_t* r, uint32_t addr) {
    asm volatile("ldmatrix.sync.aligned.m8n8.x4.shared.b16 {%0,%1,%2,%3}, [%4];"
                 : "=r"(r[0]), "=r"(r[1]), "=r"(r[2]), "=r"(r[3]) : "r"(addr));
}
__device__ __forceinline__ void ldsm4t(uint32_t* r, uint32_t addr) {
    asm volatile("ldmatrix.sync.aligned.m8n8.x4.trans.shared.b16 {%0,%1,%2,%3}, [%4];"
                 : "=r"(r[0]), "=r"(r[1]), "=r"(r[2]), "=r"(r[3]) : "r"(addr));
}

__device__ __forceinline__ void mma16816(float* c, const uint32_t* a, const uint32_t* b) {
    asm volatile("mma.sync.aligned.m16n8k16.row.col.f32.bf16.bf16.f32 "
                 "{%0,%1,%2,%3}, {%4,%5,%6,%7}, {%8,%9}, {%0,%1,%2,%3};"
                 : "+f"(c[0]), "+f"(c[1]), "+f"(c[2]), "+f"(c[3])
                 : "r"(a[0]), "r"(a[1]), "r"(a[2]), "r"(a[3]), "r"(b[0]), "r"(b[1]));
}

#define CP_ASYNC16(dst, src) \
    asm volatile("cp.async.cg.shared.global [%0], [%1], 16;" :: "r"(dst), "l"(src))
#define CP_COMMIT() asm volatile("cp.async.commit_group;" ::: "memory")
#define CP_WAIT0() asm volatile("cp.async.wait_group 0;" ::: "memory")
#define CP_WAIT1() asm volatile("cp.async.wait_group 1;" ::: "memory")
#define CP_WAIT2() asm volatile("cp.async.wait_group 2;" ::: "memory")

__device__ __forceinline__ uint32_t pk2(__nv_bfloat16 a, __nv_bfloat16 b) {
    return (uint32_t)__bfloat16_as_ushort(a) | ((uint32_t)__bfloat16_as_ushort(b) << 16);
}
__device__ __forceinline__ void split1(float v, __nv_bfloat16& h, __nv_bfloat16& l) {
    h = __float2bfloat16(v);
    l = __float2bfloat16(v - __bfloat162float(h));
}

// ---------------------------------------------------------------------------
// fp32 -> (bf16 hi, bf16 lo) split, vectorized x4
// ---------------------------------------------------------------------------
__global__ __launch_bounds__(256) void split_kernel(
    const float4* __restrict__ src, uint2* __restrict__ hi, uint2* __restrict__ lo, int n4)
{
    int i = blockIdx.x * blockDim.x + threadIdx.x;
    if (i >= n4) return;
    float4 v = src[i];
    __nv_bfloat16 h0, h1, h2, h3, l0, l1, l2, l3;
    split1(v.x, h0, l0); split1(v.y, h1, l1);
    split1(v.z, h2, l2); split1(v.w, h3, l3);
    hi[i] = make_uint2(pk2(h0, h1), pk2(h2, h3));
    lo[i] = make_uint2(pk2(l0, l1), pk2(l2, l3));
}

// ---------------------------------------------------------------------------
// RoPE + bf16 hi/lo split: fp32 [B,H,S,hd] -> bf16 hi/lo
// ---------------------------------------------------------------------------
__global__ __launch_bounds__(256) void rope_split(
    const float* __restrict__ X, const float* __restrict__ cosb,
    const float* __restrict__ sinb,
    __nv_bfloat16* __restrict__ Xh, __nv_bfloat16* __restrict__ Xl)
{
    const int gid = blockIdx.x * blockDim.x + threadIdx.x;
    const int p = gid & 31;
    const int r = gid >> 5;
    const int s = r & (SS - 1);
    const float c1 = cosb[s * HD + p];
    const float s1 = sinb[s * HD + p];
    const float c2 = cosb[s * HD + p + 32];
    const float s2 = sinb[s * HD + p + 32];
    const float* row = X + (size_t)r * HD;
    const float x1 = row[p];
    const float x2 = row[p + 32];
    const float v1 = x1 * c1 - x2 * s1;
    const float v2 = x2 * c2 + x1 * s2;
    __nv_bfloat16 h, l;
    split1(v1, h, l);
    Xh[(size_t)r * HD + p] = h; Xl[(size_t)r * HD + p] = l;
    split1(v2, h, l);
    Xh[(size_t)r * HD + p + 32] = h; Xl[(size_t)r * HD + p + 32] = l;
}

// ---------------------------------------------------------------------------
// HMMA bf16-split GEMM (NT) with cp.async pipeline (R5-proven).
// mode 0: fp32 row-major [M,N] ; mode 1: fp32 scatter [B,H,S,hd].
// ---------------------------------------------------------------------------
#define GK 32
#define NCHUNK (DD / GK)       // 32
#define ROWB 80
#define TILE_SB (128 * ROWB)   // 10240
#define BUF_SB (4 * TILE_SB)   // 40960
#define GEMM_SMEM (2 * BUF_SB) // 81920

__global__ __launch_bounds__(256) void gemm_mma(
    const __nv_bfloat16* __restrict__ Ah, const __nv_bfloat16* __restrict__ Al,
    const __nv_bfloat16* __restrict__ Bh, const __nv_bfloat16* __restrict__ Bl,
    const float* __restrict__ bias, float* __restrict__ C, int mode)
{
    extern __shared__ char sm[];
    const int tid  = threadIdx.x;
    const int wid  = tid >> 5;
    const int lane = tid & 31;
    const int bm = blockIdx.y * 128;
    const int bn = blockIdx.x * 128;
    const int warp_m = (wid & 1) * 64;
    const int warp_n = (wid >> 1) * 32;

    const uint32_t sb = smem_u32(sm);

    const char* gsrc[4] = {
        (const char*)(Ah + (size_t)bm * DD), (const char*)(Al + (size_t)bm * DD),
        (const char*)(Bh + (size_t)bn * DD), (const char*)(Bl + (size_t)bn * DD) };

    float acc[4][4][4];
#pragma unroll
    for (int i = 0; i < 4; i++)
#pragma unroll
        for (int j = 0; j < 4; j++)
#pragma unroll
            for (int q = 0; q < 4; q++) acc[i][j][q] = 0.0f;

    auto issue_chunk = [&](int c, int buf) {
        const int koff = c * 64;
        const uint32_t sdst = sb + buf * BUF_SB;
#pragma unroll
        for (int t = 0; t < 4; t++) {
            const char* g = gsrc[t] + koff;
#pragma unroll
            for (int i = 0; i < 2; i++) {
                int idx = i * 256 + tid;
                int row = idx >> 2, seg = idx & 3;
                CP_ASYNC16(sdst + t * TILE_SB + row * ROWB + seg * 16,
                           g + (size_t)row * 2048 + seg * 16);
            }
        }
    };

    issue_chunk(0, 0);
    CP_COMMIT();

    const int lig = lane & 7;
    const int grp = lane >> 3;

    for (int c = 0; c < NCHUNK; c++) {
        const int cur = c & 1;
        if (c + 1 < NCHUNK) { issue_chunk(c + 1, cur ^ 1); CP_COMMIT(); CP_WAIT1(); }
        else                { CP_WAIT0(); }
        __syncthreads();

        const uint32_t bufb = sb + cur * BUF_SB;
#pragma unroll
        for (int ks = 0; ks < 2; ks++) {
            uint32_t aH[4][4], aL[4][4], bH[2][4], bL[2][4];
            {
                const int arow = warp_m + (grp & 1) * 8 + lig;
                const int aseg = 2 * ks + (grp >> 1);
                const uint32_t aoff = arow * ROWB + aseg * 16;
#pragma unroll
                for (int mi = 0; mi < 4; mi++) {
                    ldsm4(aH[mi], bufb + 0 * TILE_SB + aoff + mi * (16 * ROWB));
                    ldsm4(aL[mi], bufb + 1 * TILE_SB + aoff + mi * (16 * ROWB));
                }
            }
            {
                const int brow = warp_n + (grp >> 1) * 8 + lig;
                const int bseg = 2 * ks + (grp & 1);
                const uint32_t boff = brow * ROWB + bseg * 16;
#pragma unroll
                for (int ni = 0; ni < 2; ni++) {
                    ldsm4(bH[ni], bufb + 2 * TILE_SB + boff + ni * (16 * ROWB));
                    ldsm4(bL[ni], bufb + 3 * TILE_SB + boff + ni * (16 * ROWB));
                }
            }
#pragma unroll
            for (int mi = 0; mi < 4; mi++)
#pragma unroll
                for (int nj = 0; nj < 4; nj++) {
                    const int ni = nj >> 1, pr = (nj & 1) * 2;
                    mma16816(acc[mi][nj], aH[mi], &bH[ni][pr]);
                    mma16816(acc[mi][nj], aH[mi], &bL[ni][pr]);
                    mma16816(acc[mi][nj], aL[mi], &bH[ni][pr]);
                }
        }
        __syncthreads();
    }

    const int mrow = lane >> 2;
    const int ncol = 2 * (lane & 3);
#pragma unroll
    for (int mi = 0; mi < 4; mi++) {
#pragma unroll
        for (int nj = 0; nj < 4; nj++) {
            const int m0 = bm + warp_m + mi * 16 + mrow;
            const int n  = bn + warp_n + nj * 8 + ncol;
            const float b0 = bias[n], b1 = bias[n + 1];
#pragma unroll
            for (int half = 0; half < 2; half++) {
                const int m = m0 + half * 8;
                float2 v;
                v.x = acc[mi][nj][2 * half + 0] + b0;
                v.y = acc[mi][nj][2 * half + 1] + b1;
                float* dst;
                if (mode == 0) {
                    dst = C + (size_t)m * DD + n;
                } else {
                    const int b = m >> 11, s = m & 2047;
                    const int h = n >> 6, hd0 = n & 63;
                    dst = C + (((size_t)(b * HH + h) * SS + s) * HD + hd0);
                }
                *(float2*)dst = v;
            }
        }
    }
}

// ---------------------------------------------------------------------------
// HMMA flash attention (causal), software-pipelined.
// Block = 64 q-rows of one (b,h), 4 warps, warp = 16 q-rows, BN=64 KV tiles.
// Full 3-term splits (R5 numerics): scores = QhKh+QhKl+QlKh ; PV = PhVh+PhVl+PlVh.
// Pipeline: scores(kt+1) interleaves with softmax(kt); K/V prefetch split so
// every cp.async group has >= 1 full iteration in flight.
// ---------------------------------------------------------------------------
#define FROW 144
#define KTILE (64 * FROW)        // 9216
#define FBUF (4 * KTILE)         // 36864: Kh,Kl,Vh,Vl
#define FQOFF (2 * FBUF)         // 73728
#define FSMEM (FQOFF + 2 * KTILE)  // 92160 (Qh, Ql tiles)

__global__ __launch_bounds__(128) void flash_mma(
    const __nv_bfloat16* __restrict__ Qh, const __nv_bfloat16* __restrict__ Ql,
    const __nv_bfloat16* __restrict__ Kh, const __nv_bfloat16* __restrict__ Kl,
    const __nv_bfloat16* __restrict__ Vh, const __nv_bfloat16* __restrict__ Vl,
    __nv_bfloat16* __restrict__ ctx_h, __nv_bfloat16* __restrict__ ctx_l)
{
    extern __shared__ char sm[];
    const int tid  = threadIdx.x;
    const int wid  = tid >> 5;      // 0..3
    const int lane = tid & 31;
    const int qb = blockIdx.x;      // 0..31
    const int bh = blockIdx.y;      // 0..63
    const uint32_t sb = smem_u32(sm);
    const size_t bhoff = (size_t)bh * SS * HD;

    const int lig = lane & 7;
    const int grp = lane >> 3;

    auto issue_k = [&](int kt, int buf) {
        const char* s0 = (const char*)(Kh + bhoff + (size_t)kt * 64 * HD);
        const char* s1 = (const char*)(Kl + bhoff + (size_t)kt * 64 * HD);
        const uint32_t d = sb + buf * FBUF;
        int idx = tid;
#pragma unroll
        for (int i = 0; i < 4; i++) {
            int row = idx >> 3, seg = idx & 7;
            CP_ASYNC16(d + row * FROW + seg * 16,         s0 + row * 128 + seg * 16);
            CP_ASYNC16(d + KTILE + row * FROW + seg * 16, s1 + row * 128 + seg * 16);
            idx += 128;
        }
    };
    auto issue_v = [&](int kt, int buf) {
        const char* s0 = (const char*)(Vh + bhoff + (size_t)kt * 64 * HD);
        const char* s1 = (const char*)(Vl + bhoff + (size_t)kt * 64 * HD);
        const uint32_t d = sb + buf * FBUF + 2 * KTILE;
        int idx = tid;
#pragma unroll
        for (int i = 0; i < 4; i++) {
            int row = idx >> 3, seg = idx & 7;
            CP_ASYNC16(d + row * FROW + seg * 16,         s0 + row * 128 + seg * 16);
            CP_ASYNC16(d + KTILE + row * FROW + seg * 16, s1 + row * 128 + seg * 16);
            idx += 128;
        }
    };

    // ---- prologue: KV(0), KV(1), Q ----
    issue_k(0, 0); issue_v(0, 0); CP_COMMIT();
    if (qb > 0) { issue_k(1, 1); issue_v(1, 1); CP_COMMIT(); }
    {
        const char* q0 = (const char*)(Qh + bhoff + (size_t)qb * 64 * HD);
        const char* q1 = (const char*)(Ql + bhoff + (size_t)qb * 64 * HD);
        int idx = tid;
#pragma unroll
        for (int i = 0; i < 4; i++) {
            int row = idx >> 3, seg = idx & 7;
            CP_ASYNC16(sb + FQOFF + row * FROW + seg * 16,         q0 + row * 128 + seg * 16);
            CP_ASYNC16(sb + FQOFF + KTILE + row * FROW + seg * 16, q1 + row * 128 + seg * 16);
            idx += 128;
        }
        CP_COMMIT();
    }
    CP_WAIT0();
    __syncthreads();

    // Q fragments (persistent, hi + lo)
    uint32_t qh_f[4][4], ql_f[4][4];
    {
        const int qrow = wid * 16 + (grp & 1) * 8 + lig;
        const uint32_t qa = sb + FQOFF + qrow * FROW;
#pragma unroll
        for (int kc = 0; kc < 4; kc++) {
            const uint32_t off = (2 * kc + (grp >> 1)) * 16;
            ldsm4(qh_f[kc], qa + off);
            ldsm4(ql_f[kc], qa + KTILE + off);
        }
    }

    auto compute_scores = [&](uint32_t kbase, float (*sc)[4]) {
#pragma unroll
        for (int nt = 0; nt < 8; nt++)
#pragma unroll
            for (int q = 0; q < 4; q++) sc[nt][q] = 0.0f;
#pragma unroll
        for (int kc = 0; kc < 4; kc++) {
            uint32_t kh_f[4][4], kl_f[4][4];
            const int krow = (grp >> 1) * 8 + lig;
            const int kseg = 2 * kc + (grp & 1);
#pragma unroll
            for (int p = 0; p < 4; p++) {
                const uint32_t a = kbase + (krow + p * 16) * FROW + kseg * 16;
                ldsm4(kh_f[p], a);
                ldsm4(kl_f[p], a + KTILE);
            }
#pragma unroll
            for (int nt = 0; nt < 8; nt++) {
                const int p = nt >> 1, pr = (nt & 1) * 2;
                mma16816(sc[nt], qh_f[kc], &kh_f[p][pr]);
                mma16816(sc[nt], qh_f[kc], &kl_f[p][pr]);
                mma16816(sc[nt], ql_f[kc], &kh_f[p][pr]);
            }
        }
    };

    float o[8][4];
#pragma unroll
    for (int nt = 0; nt < 8; nt++)
#pragma unroll
        for (int q = 0; q < 4; q++) o[nt][q] = 0.0f;
    float m0 = -1e30f, m1 = -1e30f, l0 = 0.0f, l1 = 0.0f;

    uint32_t ph_f[4][4], pl_f[4][4];

    auto softmax_P = [&](float (*sc)[4], bool mask) {
#pragma unroll
        for (int nt = 0; nt < 8; nt++)
#pragma unroll
            for (int q = 0; q < 4; q++) sc[nt][q] *= 0.125f;
        if (mask) {
            const int rloc = wid * 16 + (lane >> 2);
#pragma unroll
            for (int nt = 0; nt < 8; nt++)
#pragma unroll
                for (int q = 0; q < 4; q++) {
                    const int col = nt * 8 + 2 * (lane & 3) + (q & 1);
                    const int row = rloc + ((q >> 1) << 3);
                    if (col > row) sc[nt][q] = -1e30f;
                }
        }
        float mx0 = -1e30f, mx1 = -1e30f;
#pragma unroll
        for (int nt = 0; nt < 8; nt++) {
            mx0 = fmaxf(mx0, fmaxf(sc[nt][0], sc[nt][1]));
            mx1 = fmaxf(mx1, fmaxf(sc[nt][2], sc[nt][3]));
        }
        mx0 = fmaxf(mx0, __shfl_xor_sync(0xffffffff, mx0, 1));
        mx0 = fmaxf(mx0, __shfl_xor_sync(0xffffffff, mx0, 2));
        mx1 = fmaxf(mx1, __shfl_xor_sync(0xffffffff, mx1, 1));
        mx1 = fmaxf(mx1, __shfl_xor_sync(0xffffffff, mx1, 2));

        const float mn0 = fmaxf(m0, mx0);
        const float mn1 = fmaxf(m1, mx1);
        const float c0 = __expf(m0 - mn0);
        const float c1 = __expf(m1 - mn1);
        m0 = mn0; m1 = mn1;
        l0 *= c0; l1 *= c1;
#pragma unroll
        for (int nt = 0; nt < 8; nt++) {
            o[nt][0] *= c0; o[nt][1] *= c0;
            o[nt][2] *= c1; o[nt][3] *= c1;
        }
#pragma unroll
        for (int nt = 0; nt < 8; nt++) {
            const float p0 = __expf(sc[nt][0] - mn0);
            const float p1 = __expf(sc[nt][1] - mn0);
            const float p2 = __expf(sc[nt][2] - mn1);
            const float p3 = __expf(sc[nt][3] - mn1);
            l0 += p0 + p1;
            l1 += p2 + p3;
            __nv_bfloat16 h0, h1, h2, h3, e0, e1, e2, e3;
            split1(p0, h0, e0); split1(p1, h1, e1);
            split1(p2, h2, e2); split1(p3, h3, e3);
            const int kc = nt >> 1, hf = (nt & 1) * 2;
            ph_f[kc][hf + 0] = pk2(h0, h1);
            ph_f[kc][hf + 1] = pk2(h2, h3);
            pl_f[kc][hf + 0] = pk2(e0, e1);
            pl_f[kc][hf + 1] = pk2(e2, e3);
        }
    };

    auto compute_pv = [&](uint32_t vbase) {
#pragma unroll
        for (int kc = 0; kc < 4; kc++) {
            uint32_t vh_f[4][4], vl_f[4][4];
            const int vrow = kc * 16 + (grp & 1) * 8 + lig;
#pragma unroll
            for (int p = 0; p < 4; p++) {
                const uint32_t a = vbase + vrow * FROW + (2 * p + (grp >> 1)) * 16;
                ldsm4t(vh_f[p], a);
                ldsm4t(vl_f[p], a + KTILE);
            }
#pragma unroll
            for (int nt = 0; nt < 8; nt++) {
                const int p = nt >> 1, pr = (nt & 1) * 2;
                mma16816(o[nt], ph_f[kc], &vh_f[p][pr]);
                mma16816(o[nt], ph_f[kc], &vl_f[p][pr]);
                mma16816(o[nt], pl_f[kc], &vh_f[p][pr]);
            }
        }
    };

    // scores(0) from buffer 0
    float sc_cur[8][4];
    compute_scores(sb, sc_cur);

    for (int kt = 0; kt <= qb; kt++) {
        const int cur = kt & 1;
        if (kt < qb) {
            // K(kt+2): its K-buffer slot holds K(kt), dead since last iteration.
            if (kt + 2 <= qb) { issue_k(kt + 2, cur); CP_COMMIT(); }
            // Drain so that K(kt+1) and V(kt) are resident; leave newest 2 groups.
            if (kt + 2 <= qb) CP_WAIT2(); else CP_WAIT1();
            __syncthreads();

            // Interleaved region: scores(kt+1) MMAs + softmax(kt) scalar chain
            // (independent streams; ptxas schedules FMA/MUFU into MMA shadow).
            float sc_nxt[8][4];
            compute_scores(sb + (cur ^ 1) * FBUF, sc_nxt);
            softmax_P(sc_cur, false);
            compute_pv(sb + cur * FBUF + 2 * KTILE);
            __syncthreads();
            if (kt + 2 <= qb) { issue_v(kt + 2, cur); CP_COMMIT(); }
#pragma unroll
            for (int nt = 0; nt < 8; nt++)
#pragma unroll
                for (int q = 0; q < 4; q++) sc_cur[nt][q] = sc_nxt[nt][q];
        } else {
            softmax_P(sc_cur, true);
            CP_WAIT0();
            __syncthreads();
            compute_pv(sb + cur * FBUF + 2 * KTILE);
        }
    }

    // ---- finalize ----
    l0 += __shfl_xor_sync(0xffffffff, l0, 1);
    l0 += __shfl_xor_sync(0xffffffff, l0, 2);
    l1 += __shfl_xor_sync(0xffffffff, l1, 1);
    l1 += __shfl_xor_sync(0xffffffff, l1, 2);
    const float i0 = 1.0f / l0;
    const float i1 = 1.0f / l1;

    const int b = bh >> 4;
    const int h = bh & 15;
    const int s0 = qb * 64 + wid * 16 + (lane >> 2);
    const int s1 = s0 + 8;
#pragma unroll
    for (int nt = 0; nt < 8; nt++) {
        const int col = h * 64 + nt * 8 + 2 * (lane & 3);
        const size_t idx0 = ((size_t)(b * SS + s0)) * DD + col;
        const size_t idx1 = ((size_t)(b * SS + s1)) * DD + col;
        __nv_bfloat16 h0, h1, e0, e1;
        split1(o[nt][0] * i0, h0, e0); split1(o[nt][1] * i0, h1, e1);
        *(uint32_t*)(ctx_h + idx0) = pk2(h0, h1);
        *(uint32_t*)(ctx_l + idx0) = pk2(e0, e1);
        split1(o[nt][2] * i1, h0, e0); split1(o[nt][3] * i1, h1, e1);
        *(uint32_t*)(ctx_h + idx1) = pk2(h0, h1);
        *(uint32_t*)(ctx_l + idx1) = pk2(e0, e1);
    }
}

// ---------------------------------------------------------------------------
// Launch
// ---------------------------------------------------------------------------
extern "C" void kernel_launch(void* const* d_in, const int* in_sizes, int n_in,
                              void* d_out, int out_size)
{
    const float* x    = (const float*)d_in[0];
    const float* cosb = (const float*)d_in[2];
    const float* sinb = (const float*)d_in[3];
    const float* Wq = (const float*)d_in[4];
    const float* bq = (const float*)d_in[5];
    const float* Wk = (const float*)d_in[6];
    const float* bk = (const float*)d_in[7];
    const float* Wv = (const float*)d_in[8];
    const float* bv = (const float*)d_in[9];
    const float* Wo = (const float*)d_in[10];
    const float* bo = (const float*)d_in[11];
    float* out = (float*)d_out;

    float *Qb, *Kb, *Vb;
    __nv_bfloat16 *xh, *xl, *wh, *wl, *ch, *cl, *qh, *ql, *kh, *kl, *vh, *vl;
    cudaGetSymbolAddress((void**)&Qb, g_Q);
    cudaGetSymbolAddress((void**)&Kb, g_K);
    cudaGetSymbolAddress((void**)&Vb, g_V);
    cudaGetSymbolAddress((void**)&xh, g_xh);
    cudaGetSymbolAddress((void**)&xl, g_xl);
    cudaGetSymbolAddress((void**)&wh, g_wh);
    cudaGetSymbolAddress((void**)&wl, g_wl);
    cudaGetSymbolAddress((void**)&ch, g_ch);
    cudaGetSymbolAddress((void**)&cl, g_cl);
    cudaGetSymbolAddress((void**)&qh, g_qh);
    cudaGetSymbolAddress((void**)&ql, g_ql);
    cudaGetSymbolAddress((void**)&kh, g_kh);
    cudaGetSymbolAddress((void**)&kl, g_kl);
    cudaGetSymbolAddress((void**)&vh, g_vh);
    cudaGetSymbolAddress((void**)&vl, g_vl);

    cudaFuncSetAttribute(gemm_mma, cudaFuncAttributeMaxDynamicSharedMemorySize, GEMM_SMEM);
    cudaFuncSetAttribute(flash_mma, cudaFuncAttributeMaxDynamicSharedMemorySize, FSMEM);

    {
        int n4 = MROWS * DD / 4;
        split_kernel<<<(n4 + 255) / 256, 256>>>((const float4*)x, (uint2*)xh, (uint2*)xl, n4);
        const float* Ws[4] = {Wq, Wk, Wv, Wo};
        int w4 = DD * DD / 4;
        for (int i = 0; i < 4; i++)
            split_kernel<<<(w4 + 255) / 256, 256>>>((const float4*)Ws[i],
                (uint2*)(wh + (size_t)i * DD * DD), (uint2*)(wl + (size_t)i * DD * DD), w4);
    }

    dim3 gg(DD / 128, MROWS / 128);   // (8, 64)
    gemm_mma<<<gg, 256, GEMM_SMEM>>>(xh, xl, wh + 0 * (size_t)DD * DD, wl + 0 * (size_t)DD * DD, bq, Qb, 1);
    gemm_mma<<<gg, 256, GEMM_SMEM>>>(xh, xl, wh + 1 * (size_t)DD * DD, wl + 1 * (size_t)DD * DD, bk, Kb, 1);
    gemm_mma<<<gg, 256, GEMM_SMEM>>>(xh, xl, wh + 2 * (size_t)DD * DD, wl + 2 * (size_t)DD * DD, bv, Vb, 1);

    const int rope_threads = BB * HH * SS * 32;
    rope_split<<<rope_threads / 256, 256>>>(Qb, cosb, sinb, qh, ql);
    rope_split<<<rope_threads / 256, 256>>>(Kb, cosb, sinb, kh, kl);
    {
        int n4 = BB * HH * SS * HD / 4;
        split_kernel<<<(n4 + 255) / 256, 256>>>((const float4*)Vb, (uint2*)vh, (uint2*)vl, n4);
    }

    dim3 fg(SS / 64, BB * HH);        // (32, 64)
    flash_mma<<<fg, 128, FSMEM>>>(qh, ql, kh, kl, vh, vl, ch, cl);

    gemm_mma<<<gg, 256, GEMM_SMEM>>>(ch, cl, wh + 3 * (size_t)DD * DD, wl + 3 * (size_t)DD * DD, bo, out, 0);
}

// round 12
// speedup vs baseline: 1.1221x; 1.0138x over previous
#include <cuda_runtime.h>
#include <cuda_bf16.h>
#include <math.h>
#include <stdint.h>

// Problem constants
#define BB 4
#define SS 2048
#define DD 1024
#define HH 16
#define HD 64
#define MROWS (BB * SS)   // 8192

// ---------------------------------------------------------------------------
// Scratch (device globals: allocation-free)
// ---------------------------------------------------------------------------
__device__ float g_Q[BB * HH * SS * HD];
__device__ float g_K[BB * HH * SS * HD];
__device__ float g_V[BB * HH * SS * HD];
__device__ __align__(16) __nv_bfloat16 g_xh[MROWS * DD];
__device__ __align__(16) __nv_bfloat16 g_xl[MROWS * DD];
__device__ __align__(16) __nv_bfloat16 g_wh[4 * DD * DD];
__device__ __align__(16) __nv_bfloat16 g_wl[4 * DD * DD];
__device__ __align__(16) __nv_bfloat16 g_ch[MROWS * DD];
__device__ __align__(16) __nv_bfloat16 g_cl[MROWS * DD];
__device__ __align__(16) __nv_bfloat16 g_qh[BB * HH * SS * HD];
__device__ __align__(16) __nv_bfloat16 g_ql[BB * HH * SS * HD];
__device__ __align__(16) __nv_bfloat16 g_kh[BB * HH * SS * HD];
__device__ __align__(16) __nv_bfloat16 g_kl[BB * HH * SS * HD];
__device__ __align__(16) __nv_bfloat16 g_vh[BB * HH * SS * HD];
__device__ __align__(16) __nv_bfloat16 g_vl[BB * HH * SS * HD];

// ---------------------------------------------------------------------------
// Helpers
// ---------------------------------------------------------------------------
__device__ __forceinline__ uint32_t smem_u32(const void* p) {
    uint32_t a;
    asm("{ .reg .u64 t; cvta.to.shared.u64 t, %1; cvt.u32.u64 %0, t; }"
        : "=r"(a) : "l"(p));
    return a;
}

__device__ __forceinline__ void ldsm4(uint32_t* r, uint32_t addr) {
    asm volatile("ldmatrix.sync.aligned.m8n8.x4.shared.b16 {%0,%1,%2,%3}, [%4];"
                 : "=r"(r[0]), "=r"(r[1]), "=r"(r[2]), "=r"(r[3]) : "r"(addr));
}
__device__ __forceinline__ void ldsm4t(uint32_t* r, uint32_t addr) {
    asm volatile("ldmatrix.sync.aligned.m8n8.x4.trans.shared.b16 {%0,%1,%2,%3}, [%4];"
                 : "=r"(r[0]), "=r"(r[1]), "=r"(r[2]), "=r"(r[3]) : "r"(addr));
}

__device__ __forceinline__ void mma16816(float* c, const uint32_t* a, const uint32_t* b) {
    asm volatile("mma.sync.aligned.m16n8k16.row.col.f32.bf16.bf16.f32 "
                 "{%0,%1,%2,%3}, {%4,%5,%6,%7}, {%8,%9}, {%0,%1,%2,%3};"
                 : "+f"(c[0]), "+f"(c[1]), "+f"(c[2]), "+f"(c[3])
                 : "r"(a[0]), "r"(a[1]), "r"(a[2]), "r"(a[3]), "r"(b[0]), "r"(b[1]));
}

#define CP_ASYNC16(dst, src) \
    asm volatile("cp.async.cg.shared.global [%0], [%1], 16;" :: "r"(dst), "l"(src))
#define CP_COMMIT() asm volatile("cp.async.commit_group;" ::: "memory")
#define CP_WAIT0() asm volatile("cp.async.wait_group 0;" ::: "memory")
#define CP_WAIT1() asm volatile("cp.async.wait_group 1;" ::: "memory")
#define CP_WAIT2() asm volatile("cp.async.wait_group 2;" ::: "memory")

__device__ __forceinline__ uint32_t pk2(__nv_bfloat16 a, __nv_bfloat16 b) {
    return (uint32_t)__bfloat16_as_ushort(a) | ((uint32_t)__bfloat16_as_ushort(b) << 16);
}
__device__ __forceinline__ void split1(float v, __nv_bfloat16& h, __nv_bfloat16& l) {
    h = __float2bfloat16(v);
    l = __float2bfloat16(v - __bfloat162float(h));
}

// ---------------------------------------------------------------------------
// fp32 -> (bf16 hi, bf16 lo) split, vectorized x4 (for x)
// ---------------------------------------------------------------------------
__global__ __launch_bounds__(256) void split_kernel(
    const float4* __restrict__ src, uint2* __restrict__ hi, uint2* __restrict__ lo, int n4)
{
    int i = blockIdx.x * blockDim.x + threadIdx.x;
    if (i >= n4) return;
    float4 v = src[i];
    __nv_bfloat16 h0, h1, h2, h3, l0, l1, l2, l3;
    split1(v.x, h0, l0); split1(v.y, h1, l1);
    split1(v.z, h2, l2); split1(v.w, h3, l3);
    hi[i] = make_uint2(pk2(h0, h1), pk2(h2, h3));
    lo[i] = make_uint2(pk2(l0, l1), pk2(l2, l3));
}

// All 4 weight matrices in one launch (grid.y selects matrix)
__global__ __launch_bounds__(256) void splitW_kernel(
    const float4* __restrict__ W0, const float4* __restrict__ W1,
    const float4* __restrict__ W2, const float4* __restrict__ W3,
    uint2* __restrict__ hi, uint2* __restrict__ lo)
{
    const int n4 = DD * DD / 4;
    int i = blockIdx.x * blockDim.x + threadIdx.x;
    if (i >= n4) return;
    const int z = blockIdx.y;
    const float4* src = (z == 0) ? W0 : (z == 1) ? W1 : (z == 2) ? W2 : W3;
    float4 v = src[i];
    __nv_bfloat16 h0, h1, h2, h3, l0, l1, l2, l3;
    split1(v.x, h0, l0); split1(v.y, h1, l1);
    split1(v.z, h2, l2); split1(v.w, h3, l3);
    const size_t o = (size_t)z * n4 + i;
    hi[o] = make_uint2(pk2(h0, h1), pk2(h2, h3));
    lo[o] = make_uint2(pk2(l0, l1), pk2(l2, l3));
}

// ---------------------------------------------------------------------------
// Fused postprocess: z=0 rope+split Q, z=1 rope+split K, z=2 split V
// ---------------------------------------------------------------------------
__global__ __launch_bounds__(256) void post_qkv(
    const float* __restrict__ Q, const float* __restrict__ K,
    const float* __restrict__ V,
    const float* __restrict__ cosb, const float* __restrict__ sinb,
    __nv_bfloat16* __restrict__ Qh, __nv_bfloat16* __restrict__ Ql,
    __nv_bfloat16* __restrict__ Kh, __nv_bfloat16* __restrict__ Kl,
    __nv_bfloat16* __restrict__ Vh, __nv_bfloat16* __restrict__ Vl)
{
    const int gid = blockIdx.x * blockDim.x + threadIdx.x;
    const int z = blockIdx.y;
    const int p = gid & 31;
    const int r = gid >> 5;
    const int s = r & (SS - 1);
    const float* X = (z == 0) ? Q : (z == 1) ? K : V;
    __nv_bfloat16* Xh = (z == 0) ? Qh : (z == 1) ? Kh : Vh;
    __nv_bfloat16* Xl = (z == 0) ? Ql : (z == 1) ? Kl : Vl;
    const float* row = X + (size_t)r * HD;
    const float x1 = row[p];
    const float x2 = row[p + 32];
    float v1, v2;
    if (z < 2) {
        const float c1 = cosb[s * HD + p];
        const float s1 = sinb[s * HD + p];
        const float c2 = cosb[s * HD + p + 32];
        const float s2 = sinb[s * HD + p + 32];
        v1 = x1 * c1 - x2 * s1;
        v2 = x2 * c2 + x1 * s2;
    } else {
        v1 = x1;
        v2 = x2;
    }
    __nv_bfloat16 h, l;
    split1(v1, h, l);
    Xh[(size_t)r * HD + p] = h; Xl[(size_t)r * HD + p] = l;
    split1(v2, h, l);
    Xh[(size_t)r * HD + p + 32] = h; Xl[(size_t)r * HD + p + 32] = l;
}

// ---------------------------------------------------------------------------
// GEMM tile configuration (R5-proven)
// ---------------------------------------------------------------------------
#define GK 32
#define NCHUNK (DD / GK)       // 32
#define ROWB 80
#define TILE_SB (128 * ROWB)   // 10240
#define BUF_SB (4 * TILE_SB)   // 40960
#define GEMM_SMEM (2 * BUF_SB) // 81920

// Shared GEMM core: accumulates acc over K with cp.async double buffering.
template <typename EpilogueFn>
__device__ __forceinline__ void gemm_core(
    const __nv_bfloat16* Ah, const __nv_bfloat16* Al,
    const __nv_bfloat16* Bh, const __nv_bfloat16* Bl,
    int bm, int bn, char* sm, EpilogueFn epi)
{
    const int tid  = threadIdx.x;
    const int wid  = tid >> 5;
    const int lane = tid & 31;
    const int warp_m = (wid & 1) * 64;
    const int warp_n = (wid >> 1) * 32;

    const uint32_t sb = smem_u32(sm);
    const char* gsrc[4] = {
        (const char*)(Ah + (size_t)bm * DD), (const char*)(Al + (size_t)bm * DD),
        (const char*)(Bh + (size_t)bn * DD), (const char*)(Bl + (size_t)bn * DD) };

    float acc[4][4][4];
#pragma unroll
    for (int i = 0; i < 4; i++)
#pragma unroll
        for (int j = 0; j < 4; j++)
#pragma unroll
            for (int q = 0; q < 4; q++) acc[i][j][q] = 0.0f;

    auto issue_chunk = [&](int c, int buf) {
        const int koff = c * 64;
        const uint32_t sdst = sb + buf * BUF_SB;
#pragma unroll
        for (int t = 0; t < 4; t++) {
            const char* g = gsrc[t] + koff;
#pragma unroll
            for (int i = 0; i < 2; i++) {
                int idx = i * 256 + tid;
                int row = idx >> 2, seg = idx & 3;
                CP_ASYNC16(sdst + t * TILE_SB + row * ROWB + seg * 16,
                           g + (size_t)row * 2048 + seg * 16);
            }
        }
    };

    issue_chunk(0, 0);
    CP_COMMIT();

    const int lig = lane & 7;
    const int grp = lane >> 3;

    for (int c = 0; c < NCHUNK; c++) {
        const int cur = c & 1;
        if (c + 1 < NCHUNK) { issue_chunk(c + 1, cur ^ 1); CP_COMMIT(); CP_WAIT1(); }
        else                { CP_WAIT0(); }
        __syncthreads();

        const uint32_t bufb = sb + cur * BUF_SB;
#pragma unroll
        for (int ks = 0; ks < 2; ks++) {
            uint32_t aH[4][4], aL[4][4], bH[2][4], bL[2][4];
            {
                const int arow = warp_m + (grp & 1) * 8 + lig;
                const int aseg = 2 * ks + (grp >> 1);
                const uint32_t aoff = arow * ROWB + aseg * 16;
#pragma unroll
                for (int mi = 0; mi < 4; mi++) {
                    ldsm4(aH[mi], bufb + 0 * TILE_SB + aoff + mi * (16 * ROWB));
                    ldsm4(aL[mi], bufb + 1 * TILE_SB + aoff + mi * (16 * ROWB));
                }
            }
            {
                const int brow = warp_n + (grp >> 1) * 8 + lig;
                const int bseg = 2 * ks + (grp & 1);
                const uint32_t boff = brow * ROWB + bseg * 16;
#pragma unroll
                for (int ni = 0; ni < 2; ni++) {
                    ldsm4(bH[ni], bufb + 2 * TILE_SB + boff + ni * (16 * ROWB));
                    ldsm4(bL[ni], bufb + 3 * TILE_SB + boff + ni * (16 * ROWB));
                }
            }
#pragma unroll
            for (int mi = 0; mi < 4; mi++)
#pragma unroll
                for (int nj = 0; nj < 4; nj++) {
                    const int ni = nj >> 1, pr = (nj & 1) * 2;
                    mma16816(acc[mi][nj], aH[mi], &bH[ni][pr]);
                    mma16816(acc[mi][nj], aH[mi], &bL[ni][pr]);
                    mma16816(acc[mi][nj], aL[mi], &bH[ni][pr]);
                }
        }
        __syncthreads();
    }

    const int mrow = lane >> 2;
    const int ncol = 2 * (lane & 3);
#pragma unroll
    for (int mi = 0; mi < 4; mi++)
#pragma unroll
        for (int nj = 0; nj < 4; nj++)
#pragma unroll
            for (int half = 0; half < 2; half++) {
                const int m = bm + warp_m + mi * 16 + mrow + half * 8;
                const int n = bn + warp_n + nj * 8 + ncol;
                epi(m, n, acc[mi][nj][2 * half + 0], acc[mi][nj][2 * half + 1]);
            }
}

// Fused QKV projection: grid (8, 64, 3)
__global__ __launch_bounds__(256) void gemm_qkv(
    const __nv_bfloat16* __restrict__ Ah, const __nv_bfloat16* __restrict__ Al,
    const __nv_bfloat16* __restrict__ Wh, const __nv_bfloat16* __restrict__ Wl,
    const float* __restrict__ bq, const float* __restrict__ bk,
    const float* __restrict__ bv,
    float* __restrict__ Qf, float* __restrict__ Kf, float* __restrict__ Vf)
{
    extern __shared__ char sm[];
    const int bm = blockIdx.y * 128;
    const int bn = blockIdx.x * 128;
    const int zi = blockIdx.z;
    const float* bias = (zi == 0) ? bq : (zi == 1) ? bk : bv;
    float* C = (zi == 0) ? Qf : (zi == 1) ? Kf : Vf;
    const __nv_bfloat16* Bh = Wh + (size_t)zi * DD * DD;
    const __nv_bfloat16* Bl = Wl + (size_t)zi * DD * DD;

    gemm_core(Ah, Al, Bh, Bl, bm, bn, sm,
        [&](int m, int n, float vx, float vy) {
            const int b = m >> 11, s = m & 2047;
            const int h = n >> 6, hd0 = n & 63;
            float* dst = C + (((size_t)(b * HH + h) * SS + s) * HD + hd0);
            *(float2*)dst = make_float2(vx + bias[n], vy + bias[n + 1]);
        });
}

// Output GEMM: fp32 row-major
__global__ __launch_bounds__(256) void gemm_out(
    const __nv_bfloat16* __restrict__ Ah, const __nv_bfloat16* __restrict__ Al,
    const __nv_bfloat16* __restrict__ Bh, const __nv_bfloat16* __restrict__ Bl,
    const float* __restrict__ bias, float* __restrict__ C)
{
    extern __shared__ char sm[];
    const int bm = blockIdx.y * 128;
    const int bn = blockIdx.x * 128;
    gemm_core(Ah, Al, Bh, Bl, bm, bn, sm,
        [&](int m, int n, float vx, float vy) {
            *(float2*)(C + (size_t)m * DD + n) =
                make_float2(vx + bias[n], vy + bias[n + 1]);
        });
}

// ---------------------------------------------------------------------------
// HMMA flash attention (causal), software-pipelined (R11-proven), exp2 softmax.
// ---------------------------------------------------------------------------
#define FROW 144
#define KTILE (64 * FROW)        // 9216
#define FBUF (4 * KTILE)         // 36864: Kh,Kl,Vh,Vl
#define FQOFF (2 * FBUF)         // 73728
#define FSMEM (FQOFF + 2 * KTILE)  // 92160
#define SCALE2 0.180336881f      // 0.125 * log2(e)

__global__ __launch_bounds__(128) void flash_mma(
    const __nv_bfloat16* __restrict__ Qh, const __nv_bfloat16* __restrict__ Ql,
    const __nv_bfloat16* __restrict__ Kh, const __nv_bfloat16* __restrict__ Kl,
    const __nv_bfloat16* __restrict__ Vh, const __nv_bfloat16* __restrict__ Vl,
    __nv_bfloat16* __restrict__ ctx_h, __nv_bfloat16* __restrict__ ctx_l)
{
    extern __shared__ char sm[];
    const int tid  = threadIdx.x;
    const int wid  = tid >> 5;
    const int lane = tid & 31;
    const int qb = blockIdx.x;
    const int bh = blockIdx.y;
    const uint32_t sb = smem_u32(sm);
    const size_t bhoff = (size_t)bh * SS * HD;

    const int lig = lane & 7;
    const int grp = lane >> 3;

    auto issue_k = [&](int kt, int buf) {
        const char* s0 = (const char*)(Kh + bhoff + (size_t)kt * 64 * HD);
        const char* s1 = (const char*)(Kl + bhoff + (size_t)kt * 64 * HD);
        const uint32_t d = sb + buf * FBUF;
        int idx = tid;
#pragma unroll
        for (int i = 0; i < 4; i++) {
            int row = idx >> 3, seg = idx & 7;
            CP_ASYNC16(d + row * FROW + seg * 16,         s0 + row * 128 + seg * 16);
            CP_ASYNC16(d + KTILE + row * FROW + seg * 16, s1 + row * 128 + seg * 16);
            idx += 128;
        }
    };
    auto issue_v = [&](int kt, int buf) {
        const char* s0 = (const char*)(Vh + bhoff + (size_t)kt * 64 * HD);
        const char* s1 = (const char*)(Vl + bhoff + (size_t)kt * 64 * HD);
        const uint32_t d = sb + buf * FBUF + 2 * KTILE;
        int idx = tid;
#pragma unroll
        for (int i = 0; i < 4; i++) {
            int row = idx >> 3, seg = idx & 7;
            CP_ASYNC16(d + row * FROW + seg * 16,         s0 + row * 128 + seg * 16);
            CP_ASYNC16(d + KTILE + row * FROW + seg * 16, s1 + row * 128 + seg * 16);
            idx += 128;
        }
    };

    issue_k(0, 0); issue_v(0, 0); CP_COMMIT();
    if (qb > 0) { issue_k(1, 1); issue_v(1, 1); CP_COMMIT(); }
    {
        const char* q0 = (const char*)(Qh + bhoff + (size_t)qb * 64 * HD);
        const char* q1 = (const char*)(Ql + bhoff + (size_t)qb * 64 * HD);
        int idx = tid;
#pragma unroll
        for (int i = 0; i < 4; i++) {
            int row = idx >> 3, seg = idx & 7;
            CP_ASYNC16(sb + FQOFF + row * FROW + seg * 16,         q0 + row * 128 + seg * 16);
            CP_ASYNC16(sb + FQOFF + KTILE + row * FROW + seg * 16, q1 + row * 128 + seg * 16);
            idx += 128;
        }
        CP_COMMIT();
    }
    CP_WAIT0();
    __syncthreads();

    uint32_t qh_f[4][4], ql_f[4][4];
    {
        const int qrow = wid * 16 + (grp & 1) * 8 + lig;
        const uint32_t qa = sb + FQOFF + qrow * FROW;
#pragma unroll
        for (int kc = 0; kc < 4; kc++) {
            const uint32_t off = (2 * kc + (grp >> 1)) * 16;
            ldsm4(qh_f[kc], qa + off);
            ldsm4(ql_f[kc], qa + KTILE + off);
        }
    }

    auto compute_scores = [&](uint32_t kbase, float (*sc)[4]) {
#pragma unroll
        for (int nt = 0; nt < 8; nt++)
#pragma unroll
            for (int q = 0; q < 4; q++) sc[nt][q] = 0.0f;
#pragma unroll
        for (int kc = 0; kc < 4; kc++) {
            uint32_t kh_f[4][4], kl_f[4][4];
            const int krow = (grp >> 1) * 8 + lig;
            const int kseg = 2 * kc + (grp & 1);
#pragma unroll
            for (int p = 0; p < 4; p++) {
                const uint32_t a = kbase + (krow + p * 16) * FROW + kseg * 16;
                ldsm4(kh_f[p], a);
                ldsm4(kl_f[p], a + KTILE);
            }
#pragma unroll
            for (int nt = 0; nt < 8; nt++) {
                const int p = nt >> 1, pr = (nt & 1) * 2;
                mma16816(sc[nt], qh_f[kc], &kh_f[p][pr]);
                mma16816(sc[nt], qh_f[kc], &kl_f[p][pr]);
                mma16816(sc[nt], ql_f[kc], &kh_f[p][pr]);
            }
        }
    };

    float o[8][4];
#pragma unroll
    for (int nt = 0; nt < 8; nt++)
#pragma unroll
        for (int q = 0; q < 4; q++) o[nt][q] = 0.0f;
    float m0 = -1e30f, m1 = -1e30f, l0 = 0.0f, l1 = 0.0f;

    uint32_t ph_f[4][4], pl_f[4][4];

    // log2-domain online softmax: sc pre-scaled by 0.125*log2(e), exp2 throughout.
    auto softmax_P = [&](float (*sc)[4], bool mask) {
#pragma unroll
        for (int nt = 0; nt < 8; nt++)
#pragma unroll
            for (int q = 0; q < 4; q++) sc[nt][q] *= SCALE2;
        if (mask) {
            const int rloc = wid * 16 + (lane >> 2);
#pragma unroll
            for (int nt = 0; nt < 8; nt++)
#pragma unroll
                for (int q = 0; q < 4; q++) {
                    const int col = nt * 8 + 2 * (lane & 3) + (q & 1);
                    const int row = rloc + ((q >> 1) << 3);
                    if (col > row) sc[nt][q] = -1e30f;
                }
        }
        float mx0 = -1e30f, mx1 = -1e30f;
#pragma unroll
        for (int nt = 0; nt < 8; nt++) {
            mx0 = fmaxf(mx0, fmaxf(sc[nt][0], sc[nt][1]));
            mx1 = fmaxf(mx1, fmaxf(sc[nt][2], sc[nt][3]));
        }
        mx0 = fmaxf(mx0, __shfl_xor_sync(0xffffffff, mx0, 1));
        mx0 = fmaxf(mx0, __shfl_xor_sync(0xffffffff, mx0, 2));
        mx1 = fmaxf(mx1, __shfl_xor_sync(0xffffffff, mx1, 1));
        mx1 = fmaxf(mx1, __shfl_xor_sync(0xffffffff, mx1, 2));

        const float mn0 = fmaxf(m0, mx0);
        const float mn1 = fmaxf(m1, mx1);
        const float c0 = exp2f(m0 - mn0);
        const float c1 = exp2f(m1 - mn1);
        m0 = mn0; m1 = mn1;
        l0 *= c0; l1 *= c1;
#pragma unroll
        for (int nt = 0; nt < 8; nt++) {
            o[nt][0] *= c0; o[nt][1] *= c0;
            o[nt][2] *= c1; o[nt][3] *= c1;
        }
#pragma unroll
        for (int nt = 0; nt < 8; nt++) {
            const float p0 = exp2f(sc[nt][0] - mn0);
            const float p1 = exp2f(sc[nt][1] - mn0);
            const float p2 = exp2f(sc[nt][2] - mn1);
            const float p3 = exp2f(sc[nt][3] - mn1);
            l0 += p0 + p1;
            l1 += p2 + p3;
            __nv_bfloat16 h0, h1, h2, h3, e0, e1, e2, e3;
            split1(p0, h0, e0); split1(p1, h1, e1);
            split1(p2, h2, e2); split1(p3, h3, e3);
            const int kc = nt >> 1, hf = (nt & 1) * 2;
            ph_f[kc][hf + 0] = pk2(h0, h1);
            ph_f[kc][hf + 1] = pk2(h2, h3);
            pl_f[kc][hf + 0] = pk2(e0, e1);
            pl_f[kc][hf + 1] = pk2(e2, e3);
        }
    };

    auto compute_pv = [&](uint32_t vbase) {
#pragma unroll
        for (int kc = 0; kc < 4; kc++) {
            uint32_t vh_f[4][4], vl_f[4][4];
            const int vrow = kc * 16 + (grp & 1) * 8 + lig;
#pragma unroll
            for (int p = 0; p < 4; p++) {
                const uint32_t a = vbase + vrow * FROW + (2 * p + (grp >> 1)) * 16;
                ldsm4t(vh_f[p], a);
                ldsm4t(vl_f[p], a + KTILE);
            }
#pragma unroll
            for (int nt = 0; nt < 8; nt++) {
                const int p = nt >> 1, pr = (nt & 1) * 2;
                mma16816(o[nt], ph_f[kc], &vh_f[p][pr]);
                mma16816(o[nt], ph_f[kc], &vl_f[p][pr]);
                mma16816(o[nt], pl_f[kc], &vh_f[p][pr]);
            }
        }
    };

    float sc_cur[8][4];
    compute_scores(sb, sc_cur);

    for (int kt = 0; kt <= qb; kt++) {
        const int cur = kt & 1;
        if (kt < qb) {
            if (kt + 2 <= qb) { issue_k(kt + 2, cur); CP_COMMIT(); }
            if (kt + 2 <= qb) CP_WAIT2(); else CP_WAIT1();
            __syncthreads();

            float sc_nxt[8][4];
            compute_scores(sb + (cur ^ 1) * FBUF, sc_nxt);
            softmax_P(sc_cur, false);
            compute_pv(sb + cur * FBUF + 2 * KTILE);
            __syncthreads();
            if (kt + 2 <= qb) { issue_v(kt + 2, cur); CP_COMMIT(); }
#pragma unroll
            for (int nt = 0; nt < 8; nt++)
#pragma unroll
                for (int q = 0; q < 4; q++) sc_cur[nt][q] = sc_nxt[nt][q];
        } else {
            softmax_P(sc_cur, true);
            CP_WAIT0();
            __syncthreads();
            compute_pv(sb + cur * FBUF + 2 * KTILE);
        }
    }

    l0 += __shfl_xor_sync(0xffffffff, l0, 1);
    l0 += __shfl_xor_sync(0xffffffff, l0, 2);
    l1 += __shfl_xor_sync(0xffffffff, l1, 1);
    l1 += __shfl_xor_sync(0xffffffff, l1, 2);
    const float i0 = 1.0f / l0;
    const float i1 = 1.0f / l1;

    const int b = bh >> 4;
    const int h = bh & 15;
    const int s0 = qb * 64 + wid * 16 + (lane >> 2);
    const int s1 = s0 + 8;
#pragma unroll
    for (int nt = 0; nt < 8; nt++) {
        const int col = h * 64 + nt * 8 + 2 * (lane & 3);
        const size_t idx0 = ((size_t)(b * SS + s0)) * DD + col;
        const size_t idx1 = ((size_t)(b * SS + s1)) * DD + col;
        __nv_bfloat16 h0, h1, e0, e1;
        split1(o[nt][0] * i0, h0, e0); split1(o[nt][1] * i0, h1, e1);
        *(uint32_t*)(ctx_h + idx0) = pk2(h0, h1);
        *(uint32_t*)(ctx_l + idx0) = pk2(e0, e1);
        split1(o[nt][2] * i1, h0, e0); split1(o[nt][3] * i1, h1, e1);
        *(uint32_t*)(ctx_h + idx1) = pk2(h0, h1);
        *(uint32_t*)(ctx_l + idx1) = pk2(e0, e1);
    }
}

// ---------------------------------------------------------------------------
// Launch
// ---------------------------------------------------------------------------
extern "C" void kernel_launch(void* const* d_in, const int* in_sizes, int n_in,
                              void* d_out, int out_size)
{
    const float* x    = (const float*)d_in[0];
    const float* cosb = (const float*)d_in[2];
    const float* sinb = (const float*)d_in[3];
    const float* Wq = (const float*)d_in[4];
    const float* bq = (const float*)d_in[5];
    const float* Wk = (const float*)d_in[6];
    const float* bk = (const float*)d_in[7];
    const float* Wv = (const float*)d_in[8];
    const float* bv = (const float*)d_in[9];
    const float* Wo = (const float*)d_in[10];
    const float* bo = (const float*)d_in[11];
    float* out = (float*)d_out;

    float *Qb, *Kb, *Vb;
    __nv_bfloat16 *xh, *xl, *wh, *wl, *ch, *cl, *qh, *ql, *kh, *kl, *vh, *vl;
    cudaGetSymbolAddress((void**)&Qb, g_Q);
    cudaGetSymbolAddress((void**)&Kb, g_K);
    cudaGetSymbolAddress((void**)&Vb, g_V);
    cudaGetSymbolAddress((void**)&xh, g_xh);
    cudaGetSymbolAddress((void**)&xl, g_xl);
    cudaGetSymbolAddress((void**)&wh, g_wh);
    cudaGetSymbolAddress((void**)&wl, g_wl);
    cudaGetSymbolAddress((void**)&ch, g_ch);
    cudaGetSymbolAddress((void**)&cl, g_cl);
    cudaGetSymbolAddress((void**)&qh, g_qh);
    cudaGetSymbolAddress((void**)&ql, g_ql);
    cudaGetSymbolAddress((void**)&kh, g_kh);
    cudaGetSymbolAddress((void**)&kl, g_kl);
    cudaGetSymbolAddress((void**)&vh, g_vh);
    cudaGetSymbolAddress((void**)&vl, g_vl);

    cudaFuncSetAttribute(gemm_qkv, cudaFuncAttributeMaxDynamicSharedMemorySize, GEMM_SMEM);
    cudaFuncSetAttribute(gemm_out, cudaFuncAttributeMaxDynamicSharedMemorySize, GEMM_SMEM);
    cudaFuncSetAttribute(flash_mma, cudaFuncAttributeMaxDynamicSharedMemorySize, FSMEM);

    // Splits: x (1 launch), 4 weights (1 launch)
    {
        int n4 = MROWS * DD / 4;
        split_kernel<<<(n4 + 255) / 256, 256>>>((const float4*)x, (uint2*)xh, (uint2*)xl, n4);
        int w4 = DD * DD / 4;
        dim3 gw((w4 + 255) / 256, 4);
        splitW_kernel<<<gw, 256>>>((const float4*)Wq, (const float4*)Wk,
                                   (const float4*)Wv, (const float4*)Wo,
                                   (uint2*)wh, (uint2*)wl);
    }

    // QKV projections: one z=3 launch
    dim3 gq(DD / 128, MROWS / 128, 3);
    gemm_qkv<<<gq, 256, GEMM_SMEM>>>(xh, xl, wh, wl, bq, bk, bv, Qb, Kb, Vb);

    // RoPE+split Q/K, split V: one z=3 launch
    {
        dim3 gp(BB * HH * SS * 32 / 256, 3);
        post_qkv<<<gp, 256>>>(Qb, Kb, Vb, cosb, sinb, qh, ql, kh, kl, vh, vl);
    }

    dim3 fg(SS / 64, BB * HH);
    flash_mma<<<fg, 128, FSMEM>>>(qh, ql, kh, kl, vh, vl, ch, cl);

    dim3 gg(DD / 128, MROWS / 128);
    gemm_out<<<gg, 256, GEMM_SMEM>>>(ch, cl, wh + 3 * (size_t)DD * DD,
                                     wl + 3 * (size_t)DD * DD, bo, out);
}

// round 13
// speedup vs baseline: 1.1361x; 1.0125x over previous
#include <cuda_runtime.h>
#include <cuda_bf16.h>
#include <math.h>
#include <stdint.h>

// Problem constants
#define BB 4
#define SS 2048
#define DD 1024
#define HH 16
#define HD 64
#define MROWS (BB * SS)   // 8192

// ---------------------------------------------------------------------------
// Scratch (device globals: allocation-free)
// ---------------------------------------------------------------------------
__device__ float g_Q[BB * HH * SS * HD];
__device__ float g_K[BB * HH * SS * HD];
__device__ __align__(16) __nv_bfloat16 g_xh[MROWS * DD];
__device__ __align__(16) __nv_bfloat16 g_xl[MROWS * DD];
__device__ __align__(16) __nv_bfloat16 g_wh[4 * DD * DD];
__device__ __align__(16) __nv_bfloat16 g_wl[4 * DD * DD];
__device__ __align__(16) __nv_bfloat16 g_ch[MROWS * DD];
__device__ __align__(16) __nv_bfloat16 g_cl[MROWS * DD];
__device__ __align__(16) __nv_bfloat16 g_qh[BB * HH * SS * HD];
__device__ __align__(16) __nv_bfloat16 g_ql[BB * HH * SS * HD];
__device__ __align__(16) __nv_bfloat16 g_kh[BB * HH * SS * HD];
__device__ __align__(16) __nv_bfloat16 g_kl[BB * HH * SS * HD];
__device__ __align__(16) __nv_bfloat16 g_vh[BB * HH * SS * HD];
__device__ __align__(16) __nv_bfloat16 g_vl[BB * HH * SS * HD];

// ---------------------------------------------------------------------------
// Helpers
// ---------------------------------------------------------------------------
__device__ __forceinline__ uint32_t smem_u32(const void* p) {
    uint32_t a;
    asm("{ .reg .u64 t; cvta.to.shared.u64 t, %1; cvt.u32.u64 %0, t; }"
        : "=r"(a) : "l"(p));
    return a;
}

__device__ __forceinline__ void ldsm4(uint32_t* r, uint32_t addr) {
    asm volatile("ldmatrix.sync.aligned.m8n8.x4.shared.b16 {%0,%1,%2,%3}, [%4];"
                 : "=r"(r[0]), "=r"(r[1]), "=r"(r[2]), "=r"(r[3]) : "r"(addr));
}
__device__ __forceinline__ void ldsm4t(uint32_t* r, uint32_t addr) {
    asm volatile("ldmatrix.sync.aligned.m8n8.x4.trans.shared.b16 {%0,%1,%2,%3}, [%4];"
                 : "=r"(r[0]), "=r"(r[1]), "=r"(r[2]), "=r"(r[3]) : "r"(addr));
}

__device__ __forceinline__ void mma16816(float* c, const uint32_t* a, const uint32_t* b) {
    asm volatile("mma.sync.aligned.m16n8k16.row.col.f32.bf16.bf16.f32 "
                 "{%0,%1,%2,%3}, {%4,%5,%6,%7}, {%8,%9}, {%0,%1,%2,%3};"
                 : "+f"(c[0]), "+f"(c[1]), "+f"(c[2]), "+f"(c[3])
                 : "r"(a[0]), "r"(a[1]), "r"(a[2]), "r"(a[3]), "r"(b[0]), "r"(b[1]));
}

#define CP_ASYNC16(dst, src) \
    asm volatile("cp.async.cg.shared.global [%0], [%1], 16;" :: "r"(dst), "l"(src))
#define CP_COMMIT() asm volatile("cp.async.commit_group;" ::: "memory")
#define CP_WAIT0() asm volatile("cp.async.wait_group 0;" ::: "memory")
#define CP_WAIT1() asm volatile("cp.async.wait_group 1;" ::: "memory")
#define CP_WAIT2() asm volatile("cp.async.wait_group 2;" ::: "memory")

__device__ __forceinline__ uint32_t pk2(__nv_bfloat16 a, __nv_bfloat16 b) {
    return (uint32_t)__bfloat16_as_ushort(a) | ((uint32_t)__bfloat16_as_ushort(b) << 16);
}
__device__ __forceinline__ void split1(float v, __nv_bfloat16& h, __nv_bfloat16& l) {
    h = __float2bfloat16(v);
    l = __float2bfloat16(v - __bfloat162float(h));
}

// ---------------------------------------------------------------------------
// fp32 -> (bf16 hi, bf16 lo) split, vectorized x4 (for x)
// ---------------------------------------------------------------------------
__global__ __launch_bounds__(256) void split_kernel(
    const float4* __restrict__ src, uint2* __restrict__ hi, uint2* __restrict__ lo, int n4)
{
    int i = blockIdx.x * blockDim.x + threadIdx.x;
    if (i >= n4) return;
    float4 v = src[i];
    __nv_bfloat16 h0, h1, h2, h3, l0, l1, l2, l3;
    split1(v.x, h0, l0); split1(v.y, h1, l1);
    split1(v.z, h2, l2); split1(v.w, h3, l3);
    hi[i] = make_uint2(pk2(h0, h1), pk2(h2, h3));
    lo[i] = make_uint2(pk2(l0, l1), pk2(l2, l3));
}

// All 4 weight matrices in one launch (grid.y selects matrix)
__global__ __launch_bounds__(256) void splitW_kernel(
    const float4* __restrict__ W0, const float4* __restrict__ W1,
    const float4* __restrict__ W2, const float4* __restrict__ W3,
    uint2* __restrict__ hi, uint2* __restrict__ lo)
{
    const int n4 = DD * DD / 4;
    int i = blockIdx.x * blockDim.x + threadIdx.x;
    if (i >= n4) return;
    const int z = blockIdx.y;
    const float4* src = (z == 0) ? W0 : (z == 1) ? W1 : (z == 2) ? W2 : W3;
    float4 v = src[i];
    __nv_bfloat16 h0, h1, h2, h3, l0, l1, l2, l3;
    split1(v.x, h0, l0); split1(v.y, h1, l1);
    split1(v.z, h2, l2); split1(v.w, h3, l3);
    const size_t o = (size_t)z * n4 + i;
    hi[o] = make_uint2(pk2(h0, h1), pk2(h2, h3));
    lo[o] = make_uint2(pk2(l0, l1), pk2(l2, l3));
}

// ---------------------------------------------------------------------------
// RoPE + split for Q (z=0) and K (z=1), fully coalesced:
// thread owns 4 contiguous cols of each rope half (float4 loads, uint2 stores).
// ---------------------------------------------------------------------------
__global__ __launch_bounds__(256) void post_qk(
    const float* __restrict__ Q, const float* __restrict__ K,
    const float* __restrict__ cosb, const float* __restrict__ sinb,
    __nv_bfloat16* __restrict__ Qh, __nv_bfloat16* __restrict__ Ql,
    __nv_bfloat16* __restrict__ Kh, __nv_bfloat16* __restrict__ Kl)
{
    const int gid = blockIdx.x * blockDim.x + threadIdx.x;
    const int z = blockIdx.y;
    const int r = gid >> 3;            // row in [B*H*S)
    const int p = (gid & 7) * 4;       // col in {0,4,...,28}
    const int s = r & (SS - 1);
    const float* X = z ? K : Q;
    __nv_bfloat16* Xh = z ? Kh : Qh;
    __nv_bfloat16* Xl = z ? Kl : Ql;

    const size_t base = (size_t)r * HD;
    float4 x1 = *(const float4*)(X + base + p);
    float4 x2 = *(const float4*)(X + base + p + 32);
    float4 c1 = *(const float4*)(cosb + s * HD + p);
    float4 s1 = *(const float4*)(sinb + s * HD + p);
    float4 c2 = *(const float4*)(cosb + s * HD + p + 32);
    float4 s2 = *(const float4*)(sinb + s * HD + p + 32);

    float v1[4] = { x1.x * c1.x - x2.x * s1.x, x1.y * c1.y - x2.y * s1.y,
                    x1.z * c1.z - x2.z * s1.z, x1.w * c1.w - x2.w * s1.w };
    float v2[4] = { x2.x * c2.x + x1.x * s2.x, x2.y * c2.y + x1.y * s2.y,
                    x2.z * c2.z + x1.z * s2.z, x2.w * c2.w + x1.w * s2.w };

    __nv_bfloat16 hh[4], ll[4];
#pragma unroll
    for (int q = 0; q < 4; q++) split1(v1[q], hh[q], ll[q]);
    *(uint2*)(Xh + base + p) = make_uint2(pk2(hh[0], hh[1]), pk2(hh[2], hh[3]));
    *(uint2*)(Xl + base + p) = make_uint2(pk2(ll[0], ll[1]), pk2(ll[2], ll[3]));
#pragma unroll
    for (int q = 0; q < 4; q++) split1(v2[q], hh[q], ll[q]);
    *(uint2*)(Xh + base + p + 32) = make_uint2(pk2(hh[0], hh[1]), pk2(hh[2], hh[3]));
    *(uint2*)(Xl + base + p + 32) = make_uint2(pk2(ll[0], ll[1]), pk2(ll[2], ll[3]));
}

// ---------------------------------------------------------------------------
// GEMM tile configuration (R5-proven)
// ---------------------------------------------------------------------------
#define GK 32
#define NCHUNK (DD / GK)       // 32
#define ROWB 80
#define TILE_SB (128 * ROWB)   // 10240
#define BUF_SB (4 * TILE_SB)   // 40960
#define GEMM_SMEM (2 * BUF_SB) // 81920

template <typename EpilogueFn>
__device__ __forceinline__ void gemm_core(
    const __nv_bfloat16* Ah, const __nv_bfloat16* Al,
    const __nv_bfloat16* Bh, const __nv_bfloat16* Bl,
    int bm, int bn, char* sm, EpilogueFn epi)
{
    const int tid  = threadIdx.x;
    const int wid  = tid >> 5;
    const int lane = tid & 31;
    const int warp_m = (wid & 1) * 64;
    const int warp_n = (wid >> 1) * 32;

    const uint32_t sb = smem_u32(sm);
    const char* gsrc[4] = {
        (const char*)(Ah + (size_t)bm * DD), (const char*)(Al + (size_t)bm * DD),
        (const char*)(Bh + (size_t)bn * DD), (const char*)(Bl + (size_t)bn * DD) };

    float acc[4][4][4];
#pragma unroll
    for (int i = 0; i < 4; i++)
#pragma unroll
        for (int j = 0; j < 4; j++)
#pragma unroll
            for (int q = 0; q < 4; q++) acc[i][j][q] = 0.0f;

    auto issue_chunk = [&](int c, int buf) {
        const int koff = c * 64;
        const uint32_t sdst = sb + buf * BUF_SB;
#pragma unroll
        for (int t = 0; t < 4; t++) {
            const char* g = gsrc[t] + koff;
#pragma unroll
            for (int i = 0; i < 2; i++) {
                int idx = i * 256 + tid;
                int row = idx >> 2, seg = idx & 3;
                CP_ASYNC16(sdst + t * TILE_SB + row * ROWB + seg * 16,
                           g + (size_t)row * 2048 + seg * 16);
            }
        }
    };

    issue_chunk(0, 0);
    CP_COMMIT();

    const int lig = lane & 7;
    const int grp = lane >> 3;

    for (int c = 0; c < NCHUNK; c++) {
        const int cur = c & 1;
        if (c + 1 < NCHUNK) { issue_chunk(c + 1, cur ^ 1); CP_COMMIT(); CP_WAIT1(); }
        else                { CP_WAIT0(); }
        __syncthreads();

        const uint32_t bufb = sb + cur * BUF_SB;
#pragma unroll
        for (int ks = 0; ks < 2; ks++) {
            uint32_t aH[4][4], aL[4][4], bH[2][4], bL[2][4];
            {
                const int arow = warp_m + (grp & 1) * 8 + lig;
                const int aseg = 2 * ks + (grp >> 1);
                const uint32_t aoff = arow * ROWB + aseg * 16;
#pragma unroll
                for (int mi = 0; mi < 4; mi++) {
                    ldsm4(aH[mi], bufb + 0 * TILE_SB + aoff + mi * (16 * ROWB));
                    ldsm4(aL[mi], bufb + 1 * TILE_SB + aoff + mi * (16 * ROWB));
                }
            }
            {
                const int brow = warp_n + (grp >> 1) * 8 + lig;
                const int bseg = 2 * ks + (grp & 1);
                const uint32_t boff = brow * ROWB + bseg * 16;
#pragma unroll
                for (int ni = 0; ni < 2; ni++) {
                    ldsm4(bH[ni], bufb + 2 * TILE_SB + boff + ni * (16 * ROWB));
                    ldsm4(bL[ni], bufb + 3 * TILE_SB + boff + ni * (16 * ROWB));
                }
            }
#pragma unroll
            for (int mi = 0; mi < 4; mi++)
#pragma unroll
                for (int nj = 0; nj < 4; nj++) {
                    const int ni = nj >> 1, pr = (nj & 1) * 2;
                    mma16816(acc[mi][nj], aH[mi], &bH[ni][pr]);
                    mma16816(acc[mi][nj], aH[mi], &bL[ni][pr]);
                    mma16816(acc[mi][nj], aL[mi], &bH[ni][pr]);
                }
        }
        __syncthreads();
    }

    const int mrow = lane >> 2;
    const int ncol = 2 * (lane & 3);
#pragma unroll
    for (int mi = 0; mi < 4; mi++)
#pragma unroll
        for (int nj = 0; nj < 4; nj++)
#pragma unroll
            for (int half = 0; half < 2; half++) {
                const int m = bm + warp_m + mi * 16 + mrow + half * 8;
                const int n = bn + warp_n + nj * 8 + ncol;
                epi(m, n, acc[mi][nj][2 * half + 0], acc[mi][nj][2 * half + 1]);
            }
}

// Fused QKV projection: grid (8, 64, 3).
// z=0/1 -> fp32 scatter (Q/K, rope applied later); z=2 -> bf16 hi/lo scatter (V).
__global__ __launch_bounds__(256) void gemm_qkv(
    const __nv_bfloat16* __restrict__ Ah, const __nv_bfloat16* __restrict__ Al,
    const __nv_bfloat16* __restrict__ Wh, const __nv_bfloat16* __restrict__ Wl,
    const float* __restrict__ bq, const float* __restrict__ bk,
    const float* __restrict__ bv,
    float* __restrict__ Qf, float* __restrict__ Kf,
    __nv_bfloat16* __restrict__ Vh, __nv_bfloat16* __restrict__ Vl)
{
    extern __shared__ char sm[];
    const int bm = blockIdx.y * 128;
    const int bn = blockIdx.x * 128;
    const int zi = blockIdx.z;
    const float* bias = (zi == 0) ? bq : (zi == 1) ? bk : bv;
    float* C = (zi == 0) ? Qf : Kf;
    const __nv_bfloat16* Bh = Wh + (size_t)zi * DD * DD;
    const __nv_bfloat16* Bl = Wl + (size_t)zi * DD * DD;

    gemm_core(Ah, Al, Bh, Bl, bm, bn, sm,
        [&](int m, int n, float vx, float vy) {
            const int b = m >> 11, s = m & 2047;
            const int h = n >> 6, hd0 = n & 63;
            const size_t idx = (((size_t)(b * HH + h) * SS + s) * HD + hd0);
            const float ax = vx + bias[n];
            const float ay = vy + bias[n + 1];
            if (zi < 2) {
                *(float2*)(C + idx) = make_float2(ax, ay);
            } else {
                __nv_bfloat16 h0, h1, e0, e1;
                split1(ax, h0, e0); split1(ay, h1, e1);
                *(uint32_t*)(Vh + idx) = pk2(h0, h1);
                *(uint32_t*)(Vl + idx) = pk2(e0, e1);
            }
        });
}

// Output GEMM: fp32 row-major
__global__ __launch_bounds__(256) void gemm_out(
    const __nv_bfloat16* __restrict__ Ah, const __nv_bfloat16* __restrict__ Al,
    const __nv_bfloat16* __restrict__ Bh, const __nv_bfloat16* __restrict__ Bl,
    const float* __restrict__ bias, float* __restrict__ C)
{
    extern __shared__ char sm[];
    const int bm = blockIdx.y * 128;
    const int bn = blockIdx.x * 128;
    gemm_core(Ah, Al, Bh, Bl, bm, bn, sm,
        [&](int m, int n, float vx, float vy) {
            *(float2*)(C + (size_t)m * DD + n) =
                make_float2(vx + bias[n], vy + bias[n + 1]);
        });
}

// ---------------------------------------------------------------------------
// HMMA flash attention (causal), software-pipelined, exp2 softmax,
// heavy-first CTA ordering (qb = gridDim.x-1-blockIdx.x).
// ---------------------------------------------------------------------------
#define FROW 144
#define KTILE (64 * FROW)        // 9216
#define FBUF (4 * KTILE)         // 36864: Kh,Kl,Vh,Vl
#define FQOFF (2 * FBUF)         // 73728
#define FSMEM (FQOFF + 2 * KTILE)  // 92160
#define SCALE2 0.180336881f      // 0.125 * log2(e)

__global__ __launch_bounds__(128) void flash_mma(
    const __nv_bfloat16* __restrict__ Qh, const __nv_bfloat16* __restrict__ Ql,
    const __nv_bfloat16* __restrict__ Kh, const __nv_bfloat16* __restrict__ Kl,
    const __nv_bfloat16* __restrict__ Vh, const __nv_bfloat16* __restrict__ Vl,
    __nv_bfloat16* __restrict__ ctx_h, __nv_bfloat16* __restrict__ ctx_l)
{
    extern __shared__ char sm[];
    const int tid  = threadIdx.x;
    const int wid  = tid >> 5;
    const int lane = tid & 31;
    const int qb = (gridDim.x - 1) - blockIdx.x;   // heavy tiles first
    const int bh = blockIdx.y;
    const uint32_t sb = smem_u32(sm);
    const size_t bhoff = (size_t)bh * SS * HD;

    const int lig = lane & 7;
    const int grp = lane >> 3;

    auto issue_k = [&](int kt, int buf) {
        const char* s0 = (const char*)(Kh + bhoff + (size_t)kt * 64 * HD);
        const char* s1 = (const char*)(Kl + bhoff + (size_t)kt * 64 * HD);
        const uint32_t d = sb + buf * FBUF;
        int idx = tid;
#pragma unroll
        for (int i = 0; i < 4; i++) {
            int row = idx >> 3, seg = idx & 7;
            CP_ASYNC16(d + row * FROW + seg * 16,         s0 + row * 128 + seg * 16);
            CP_ASYNC16(d + KTILE + row * FROW + seg * 16, s1 + row * 128 + seg * 16);
            idx += 128;
        }
    };
    auto issue_v = [&](int kt, int buf) {
        const char* s0 = (const char*)(Vh + bhoff + (size_t)kt * 64 * HD);
        const char* s1 = (const char*)(Vl + bhoff + (size_t)kt * 64 * HD);
        const uint32_t d = sb + buf * FBUF + 2 * KTILE;
        int idx = tid;
#pragma unroll
        for (int i = 0; i < 4; i++) {
            int row = idx >> 3, seg = idx & 7;
            CP_ASYNC16(d + row * FROW + seg * 16,         s0 + row * 128 + seg * 16);
            CP_ASYNC16(d + KTILE + row * FROW + seg * 16, s1 + row * 128 + seg * 16);
            idx += 128;
        }
    };

    issue_k(0, 0); issue_v(0, 0); CP_COMMIT();
    if (qb > 0) { issue_k(1, 1); issue_v(1, 1); CP_COMMIT(); }
    {
        const char* q0 = (const char*)(Qh + bhoff + (size_t)qb * 64 * HD);
        const char* q1 = (const char*)(Ql + bhoff + (size_t)qb * 64 * HD);
        int idx = tid;
#pragma unroll
        for (int i = 0; i < 4; i++) {
            int row = idx >> 3, seg = idx & 7;
            CP_ASYNC16(sb + FQOFF + row * FROW + seg * 16,         q0 + row * 128 + seg * 16);
            CP_ASYNC16(sb + FQOFF + KTILE + row * FROW + seg * 16, q1 + row * 128 + seg * 16);
            idx += 128;
        }
        CP_COMMIT();
    }
    CP_WAIT0();
    __syncthreads();

    uint32_t qh_f[4][4], ql_f[4][4];
    {
        const int qrow = wid * 16 + (grp & 1) * 8 + lig;
        const uint32_t qa = sb + FQOFF + qrow * FROW;
#pragma unroll
        for (int kc = 0; kc < 4; kc++) {
            const uint32_t off = (2 * kc + (grp >> 1)) * 16;
            ldsm4(qh_f[kc], qa + off);
            ldsm4(ql_f[kc], qa + KTILE + off);
        }
    }

    auto compute_scores = [&](uint32_t kbase, float (*sc)[4]) {
#pragma unroll
        for (int nt = 0; nt < 8; nt++)
#pragma unroll
            for (int q = 0; q < 4; q++) sc[nt][q] = 0.0f;
#pragma unroll
        for (int kc = 0; kc < 4; kc++) {
            uint32_t kh_f[4][4], kl_f[4][4];
            const int krow = (grp >> 1) * 8 + lig;
            const int kseg = 2 * kc + (grp & 1);
#pragma unroll
            for (int p = 0; p < 4; p++) {
                const uint32_t a = kbase + (krow + p * 16) * FROW + kseg * 16;
                ldsm4(kh_f[p], a);
                ldsm4(kl_f[p], a + KTILE);
            }
#pragma unroll
            for (int nt = 0; nt < 8; nt++) {
                const int p = nt >> 1, pr = (nt & 1) * 2;
                mma16816(sc[nt], qh_f[kc], &kh_f[p][pr]);
                mma16816(sc[nt], qh_f[kc], &kl_f[p][pr]);
                mma16816(sc[nt], ql_f[kc], &kh_f[p][pr]);
            }
        }
    };

    float o[8][4];
#pragma unroll
    for (int nt = 0; nt < 8; nt++)
#pragma unroll
        for (int q = 0; q < 4; q++) o[nt][q] = 0.0f;
    float m0 = -1e30f, m1 = -1e30f, l0 = 0.0f, l1 = 0.0f;

    uint32_t ph_f[4][4], pl_f[4][4];

    auto softmax_P = [&](float (*sc)[4], bool mask) {
#pragma unroll
        for (int nt = 0; nt < 8; nt++)
#pragma unroll
            for (int q = 0; q < 4; q++) sc[nt][q] *= SCALE2;
        if (mask) {
            const int rloc = wid * 16 + (lane >> 2);
#pragma unroll
            for (int nt = 0; nt < 8; nt++)
#pragma unroll
                for (int q = 0; q < 4; q++) {
                    const int col = nt * 8 + 2 * (lane & 3) + (q & 1);
                    const int row = rloc + ((q >> 1) << 3);
                    if (col > row) sc[nt][q] = -1e30f;
                }
        }
        float mx0 = -1e30f, mx1 = -1e30f;
#pragma unroll
        for (int nt = 0; nt < 8; nt++) {
            mx0 = fmaxf(mx0, fmaxf(sc[nt][0], sc[nt][1]));
            mx1 = fmaxf(mx1, fmaxf(sc[nt][2], sc[nt][3]));
        }
        mx0 = fmaxf(mx0, __shfl_xor_sync(0xffffffff, mx0, 1));
        mx0 = fmaxf(mx0, __shfl_xor_sync(0xffffffff, mx0, 2));
        mx1 = fmaxf(mx1, __shfl_xor_sync(0xffffffff, mx1, 1));
        mx1 = fmaxf(mx1, __shfl_xor_sync(0xffffffff, mx1, 2));

        const float mn0 = fmaxf(m0, mx0);
        const float mn1 = fmaxf(m1, mx1);
        const float c0 = exp2f(m0 - mn0);
        const float c1 = exp2f(m1 - mn1);
        m0 = mn0; m1 = mn1;
        l0 *= c0; l1 *= c1;
#pragma unroll
        for (int nt = 0; nt < 8; nt++) {
            o[nt][0] *= c0; o[nt][1] *= c0;
            o[nt][2] *= c1; o[nt][3] *= c1;
        }
#pragma unroll
        for (int nt = 0; nt < 8; nt++) {
            const float p0 = exp2f(sc[nt][0] - mn0);
            const float p1 = exp2f(sc[nt][1] - mn0);
            const float p2 = exp2f(sc[nt][2] - mn1);
            const float p3 = exp2f(sc[nt][3] - mn1);
            l0 += p0 + p1;
            l1 += p2 + p3;
            __nv_bfloat16 h0, h1, h2, h3, e0, e1, e2, e3;
            split1(p0, h0, e0); split1(p1, h1, e1);
            split1(p2, h2, e2); split1(p3, h3, e3);
            const int kc = nt >> 1, hf = (nt & 1) * 2;
            ph_f[kc][hf + 0] = pk2(h0, h1);
            ph_f[kc][hf + 1] = pk2(h2, h3);
            pl_f[kc][hf + 0] = pk2(e0, e1);
            pl_f[kc][hf + 1] = pk2(e2, e3);
        }
    };

    auto compute_pv = [&](uint32_t vbase) {
#pragma unroll
        for (int kc = 0; kc < 4; kc++) {
            uint32_t vh_f[4][4], vl_f[4][4];
            const int vrow = kc * 16 + (grp & 1) * 8 + lig;
#pragma unroll
            for (int p = 0; p < 4; p++) {
                const uint32_t a = vbase + vrow * FROW + (2 * p + (grp >> 1)) * 16;
                ldsm4t(vh_f[p], a);
                ldsm4t(vl_f[p], a + KTILE);
            }
#pragma unroll
            for (int nt = 0; nt < 8; nt++) {
                const int p = nt >> 1, pr = (nt & 1) * 2;
                mma16816(o[nt], ph_f[kc], &vh_f[p][pr]);
                mma16816(o[nt], ph_f[kc], &vl_f[p][pr]);
                mma16816(o[nt], pl_f[kc], &vh_f[p][pr]);
            }
        }
    };

    float sc_cur[8][4];
    compute_scores(sb, sc_cur);

    for (int kt = 0; kt <= qb; kt++) {
        const int cur = kt & 1;
        if (kt < qb) {
            if (kt + 2 <= qb) { issue_k(kt + 2, cur); CP_COMMIT(); }
            if (kt + 2 <= qb) CP_WAIT2(); else CP_WAIT1();
            __syncthreads();

            float sc_nxt[8][4];
            compute_scores(sb + (cur ^ 1) * FBUF, sc_nxt);
            softmax_P(sc_cur, false);
            compute_pv(sb + cur * FBUF + 2 * KTILE);
            __syncthreads();
            if (kt + 2 <= qb) { issue_v(kt + 2, cur); CP_COMMIT(); }
#pragma unroll
            for (int nt = 0; nt < 8; nt++)
#pragma unroll
                for (int q = 0; q < 4; q++) sc_cur[nt][q] = sc_nxt[nt][q];
        } else {
            softmax_P(sc_cur, true);
            CP_WAIT0();
            __syncthreads();
            compute_pv(sb + cur * FBUF + 2 * KTILE);
        }
    }

    l0 += __shfl_xor_sync(0xffffffff, l0, 1);
    l0 += __shfl_xor_sync(0xffffffff, l0, 2);
    l1 += __shfl_xor_sync(0xffffffff, l1, 1);
    l1 += __shfl_xor_sync(0xffffffff, l1, 2);
    const float i0 = 1.0f / l0;
    const float i1 = 1.0f / l1;

    const int b = bh >> 4;
    const int h = bh & 15;
    const int s0 = qb * 64 + wid * 16 + (lane >> 2);
    const int s1 = s0 + 8;
#pragma unroll
    for (int nt = 0; nt < 8; nt++) {
        const int col = h * 64 + nt * 8 + 2 * (lane & 3);
        const size_t idx0 = ((size_t)(b * SS + s0)) * DD + col;
        const size_t idx1 = ((size_t)(b * SS + s1)) * DD + col;
        __nv_bfloat16 h0, h1, e0, e1;
        split1(o[nt][0] * i0, h0, e0); split1(o[nt][1] * i0, h1, e1);
        *(uint32_t*)(ctx_h + idx0) = pk2(h0, h1);
        *(uint32_t*)(ctx_l + idx0) = pk2(e0, e1);
        split1(o[nt][2] * i1, h0, e0); split1(o[nt][3] * i1, h1, e1);
        *(uint32_t*)(ctx_h + idx1) = pk2(h0, h1);
        *(uint32_t*)(ctx_l + idx1) = pk2(e0, e1);
    }
}

// ---------------------------------------------------------------------------
// Launch
// ---------------------------------------------------------------------------
extern "C" void kernel_launch(void* const* d_in, const int* in_sizes, int n_in,
                              void* d_out, int out_size)
{
    const float* x    = (const float*)d_in[0];
    const float* cosb = (const float*)d_in[2];
    const float* sinb = (const float*)d_in[3];
    const float* Wq = (const float*)d_in[4];
    const float* bq = (const float*)d_in[5];
    const float* Wk = (const float*)d_in[6];
    const float* bk = (const float*)d_in[7];
    const float* Wv = (const float*)d_in[8];
    const float* bv = (const float*)d_in[9];
    const float* Wo = (const float*)d_in[10];
    const float* bo = (const float*)d_in[11];
    float* out = (float*)d_out;

    float *Qb, *Kb;
    __nv_bfloat16 *xh, *xl, *wh, *wl, *ch, *cl, *qh, *ql, *kh, *kl, *vh, *vl;
    cudaGetSymbolAddress((void**)&Qb, g_Q);
    cudaGetSymbolAddress((void**)&Kb, g_K);
    cudaGetSymbolAddress((void**)&xh, g_xh);
    cudaGetSymbolAddress((void**)&xl, g_xl);
    cudaGetSymbolAddress((void**)&wh, g_wh);
    cudaGetSymbolAddress((void**)&wl, g_wl);
    cudaGetSymbolAddress((void**)&ch, g_ch);
    cudaGetSymbolAddress((void**)&cl, g_cl);
    cudaGetSymbolAddress((void**)&qh, g_qh);
    cudaGetSymbolAddress((void**)&ql, g_ql);
    cudaGetSymbolAddress((void**)&kh, g_kh);
    cudaGetSymbolAddress((void**)&kl, g_kl);
    cudaGetSymbolAddress((void**)&vh, g_vh);
    cudaGetSymbolAddress((void**)&vl, g_vl);

    cudaFuncSetAttribute(gemm_qkv, cudaFuncAttributeMaxDynamicSharedMemorySize, GEMM_SMEM);
    cudaFuncSetAttribute(gemm_out, cudaFuncAttributeMaxDynamicSharedMemorySize, GEMM_SMEM);
    cudaFuncSetAttribute(flash_mma, cudaFuncAttributeMaxDynamicSharedMemorySize, FSMEM);

    // Splits: x (1 launch), 4 weights (1 launch)
    {
        int n4 = MROWS * DD / 4;
        split_kernel<<<(n4 + 255) / 256, 256>>>((const float4*)x, (uint2*)xh, (uint2*)xl, n4);
        int w4 = DD * DD / 4;
        dim3 gw((w4 + 255) / 256, 4);
        splitW_kernel<<<gw, 256>>>((const float4*)Wq, (const float4*)Wk,
                                   (const float4*)Wv, (const float4*)Wo,
                                   (uint2*)wh, (uint2*)wl);
    }

    // QKV projections: one z=3 launch; V emitted directly as bf16 hi/lo
    dim3 gq(DD / 128, MROWS / 128, 3);
    gemm_qkv<<<gq, 256, GEMM_SMEM>>>(xh, xl, wh, wl, bq, bk, bv, Qb, Kb, vh, vl);

    // RoPE+split Q/K: one z=2 launch, coalesced
    {
        dim3 gp(BB * HH * SS * 8 / 256, 2);
        post_qk<<<gp, 256>>>(Qb, Kb, cosb, sinb, qh, ql, kh, kl);
    }

    dim3 fg(SS / 64, BB * HH);
    flash_mma<<<fg, 128, FSMEM>>>(qh, ql, kh, kl, vh, vl, ch, cl);

    dim3 gg(DD / 128, MROWS / 128);
    gemm_out<<<gg, 256, GEMM_SMEM>>>(ch, cl, wh + 3 * (size_t)DD * DD,
                                     wl + 3 * (size_t)DD * DD, bo, out);
}